// round 1
// baseline (speedup 1.0000x reference)
#include <cuda_runtime.h>
#include <cuda_bf16.h>
#include <math_constants.h>

// Problem constants
#define BATCH 4
#define SEQ   2048
#define DIM   1024

// GEMM tiling
#define BM 64
#define BN 64
#define BK 16

// Scratch: Q, K, V [B, S, D] fp32 and scores/probs [B, S, S] fp32 (softmax in-place)
__device__ float g_Q[(long)BATCH * SEQ * DIM];
__device__ float g_K[(long)BATCH * SEQ * DIM];
__device__ float g_V[(long)BATCH * SEQ * DIM];
__device__ float g_S[(long)BATCH * SEQ * SEQ];

// C[M,N] = alpha * A[M,K] @ op(B)
//  TRANSB=true : op(B) = B^T with B stored [N,K] row-major (NT GEMM)
//  TRANSB=false: op(B) = B   with B stored [K,N] row-major (NN GEMM)
// CAUSAL: 0 = none; 1 = skip blocks fully above diagonal (scores, M==N tiles);
//         2 = limit k-loop to (block_row+1)*BM (P@V where P is causal-zeroed)
template<bool TRANSB, int CAUSAL>
__global__ __launch_bounds__(256)
void gemm_kernel(const float* __restrict__ A, const float* __restrict__ B,
                 float* __restrict__ C,
                 int M, int N, int K,
                 long strideA, long strideB, long strideC,
                 float alpha)
{
    if (CAUSAL == 1 && blockIdx.x > blockIdx.y) return;  // fully-masked score block

    __shared__ float As[BK][BM];
    __shared__ float Bs[BK][BN];

    A += (long)blockIdx.z * strideA;
    B += (long)blockIdx.z * strideB;
    C += (long)blockIdx.z * strideC;

    const int tid = threadIdx.x;           // 0..255
    const int tx  = tid & 15;              // 0..15  (n direction)
    const int ty  = tid >> 4;              // 0..15  (m direction)
    const int row0 = blockIdx.y * BM;
    const int col0 = blockIdx.x * BN;

    // A-tile load mapping: thread -> (m = tid/4, k = (tid%4)*4), float4 along k
    const int la_m = tid >> 2;
    const int la_k = (tid & 3) << 2;
    // NN B-tile load mapping: thread -> (k = tid/16, n = (tid%16)*4), float4 along n
    const int lb_k = tid >> 4;
    const int lb_n = (tid & 15) << 2;

    float acc[4][4] = {};

    int kEnd = K;
    if (CAUSAL == 2) {
        int lim = (blockIdx.y + 1) * BM;   // P row block ends at row0+BM-1; cols beyond are zero
        if (lim < kEnd) kEnd = lim;
    }

    for (int k0 = 0; k0 < kEnd; k0 += BK) {
        // ---- load A tile (rows m, contiguous in k) ----
        float4 a4 = *reinterpret_cast<const float4*>(&A[(long)(row0 + la_m) * K + k0 + la_k]);
        As[la_k + 0][la_m] = a4.x;
        As[la_k + 1][la_m] = a4.y;
        As[la_k + 2][la_m] = a4.z;
        As[la_k + 3][la_m] = a4.w;

        // ---- load B tile ----
        if (TRANSB) {
            // B is [N,K]: row n contiguous in k
            float4 b4 = *reinterpret_cast<const float4*>(&B[(long)(col0 + la_m) * K + k0 + la_k]);
            Bs[la_k + 0][la_m] = b4.x;
            Bs[la_k + 1][la_m] = b4.y;
            Bs[la_k + 2][la_m] = b4.z;
            Bs[la_k + 3][la_m] = b4.w;
        } else {
            // B is [K,N]: row k contiguous in n
            float4 b4 = *reinterpret_cast<const float4*>(&B[(long)(k0 + lb_k) * N + col0 + lb_n]);
            *reinterpret_cast<float4*>(&Bs[lb_k][lb_n]) = b4;
        }
        __syncthreads();

        #pragma unroll
        for (int kk = 0; kk < BK; kk++) {
            float4 av = *reinterpret_cast<const float4*>(&As[kk][ty << 2]);
            float4 bv = *reinterpret_cast<const float4*>(&Bs[kk][tx << 2]);
            float ar[4] = {av.x, av.y, av.z, av.w};
            float br[4] = {bv.x, bv.y, bv.z, bv.w};
            #pragma unroll
            for (int i = 0; i < 4; i++)
                #pragma unroll
                for (int j = 0; j < 4; j++)
                    acc[i][j] = fmaf(ar[i], br[j], acc[i][j]);
        }
        __syncthreads();
    }

    #pragma unroll
    for (int i = 0; i < 4; i++) {
        float* crow = &C[(long)(row0 + (ty << 2) + i) * N + col0 + (tx << 2)];
        #pragma unroll
        for (int j = 0; j < 4; j++)
            crow[j] = acc[i][j] * alpha;
    }
}

// Row-wise causal + pad-masked softmax, in-place on the scores buffer.
// Scores were already scaled by 1/sqrt(D) in the GEMM epilogue.
// grid = (S, B), block = 256
__global__ __launch_bounds__(256)
void softmax_kernel(float* __restrict__ Sc, const int* __restrict__ mask, int S)
{
    const int q = blockIdx.x;
    const int b = blockIdx.y;
    float* row = Sc + ((long)b * S + q) * (long)S;
    const int* mk = mask + (long)b * S;

    __shared__ float red[256];
    const int tid = threadIdx.x;

    // pass 1: max over attended cols [0, q]
    float mx = -CUDART_INF_F;
    for (int c = tid; c <= q; c += 256)
        if (mk[c]) mx = fmaxf(mx, row[c]);
    red[tid] = mx;
    __syncthreads();
    #pragma unroll
    for (int s = 128; s > 0; s >>= 1) {
        if (tid < s) red[tid] = fmaxf(red[tid], red[tid + s]);
        __syncthreads();
    }
    mx = red[0];
    __syncthreads();

    // pass 2: exp + sum, write exp in place
    float sum = 0.f;
    for (int c = tid; c <= q; c += 256) {
        float e = mk[c] ? __expf(row[c] - mx) : 0.f;
        row[c] = e;
        sum += e;
    }
    red[tid] = sum;
    __syncthreads();
    #pragma unroll
    for (int s = 128; s > 0; s >>= 1) {
        if (tid < s) red[tid] += red[tid + s];
        __syncthreads();
    }
    const float inv = 1.f / red[0];
    __syncthreads();

    // pass 3: normalize, zero the causal upper triangle (P@V reads full rows)
    for (int c = tid; c < S; c += 256)
        row[c] = (c <= q) ? row[c] * inv : 0.f;
}

extern "C" void kernel_launch(void* const* d_in, const int* in_sizes, int n_in,
                              void* d_out, int out_size)
{
    const float* x    = (const float*)d_in[0];  // [B, S, D]
    const int*   mask = (const int*)  d_in[1];  // [B, S]
    const float* Wq   = (const float*)d_in[2];  // [D, D]
    const float* Wk   = (const float*)d_in[3];
    const float* Wv   = (const float*)d_in[4];
    float* out = (float*)d_out;                 // [B, S, D]

    float *qp, *kp, *vp, *sp;
    cudaGetSymbolAddress((void**)&qp, g_Q);
    cudaGetSymbolAddress((void**)&kp, g_K);
    cudaGetSymbolAddress((void**)&vp, g_V);
    cudaGetSymbolAddress((void**)&sp, g_S);

    const int  BS  = BATCH * SEQ;               // 8192
    const long SQ  = (long)SEQ * DIM;           // per-batch Q/K/V stride
    const long SS  = (long)SEQ * SEQ;           // per-batch score stride
    const float scale = 1.0f / 32.0f;           // 1/sqrt(1024)

    dim3 blk(256);

    // QKV projections: [8192,1024] = x[8192,1024] @ W^T   (NT)
    dim3 gQKV(DIM / BN, BS / BM, 1);            // (16, 128)
    gemm_kernel<true, 0><<<gQKV, blk>>>(x, Wq, qp, BS, DIM, DIM, 0, 0, 0, 1.f);
    gemm_kernel<true, 0><<<gQKV, blk>>>(x, Wk, kp, BS, DIM, DIM, 0, 0, 0, 1.f);
    gemm_kernel<true, 0><<<gQKV, blk>>>(x, Wv, vp, BS, DIM, DIM, 0, 0, 0, 1.f);

    // Scores: per batch  S = scale * Q @ K^T  (NT, causal block skip)
    dim3 gSC(SEQ / BN, SEQ / BM, BATCH);        // (32, 32, 4)
    gemm_kernel<true, 1><<<gSC, blk>>>(qp, kp, sp, SEQ, SEQ, DIM, SQ, SQ, SS, scale);

    // Softmax (in place, causal + pad mask)
    softmax_kernel<<<dim3(SEQ, BATCH), 256>>>(sp, mask, SEQ);

    // Output: per batch  O = P @ V  (NN, k-loop causal-limited)
    dim3 gPV(DIM / BN, SEQ / BM, BATCH);        // (16, 32, 4)
    gemm_kernel<false, 2><<<gPV, blk>>>(sp, vp, out, SEQ, DIM, SEQ, SS, SQ, SQ, 1.f);
}

// round 2
// speedup vs baseline: 1.2678x; 1.2678x over previous
#include <cuda_runtime.h>
#include <cuda_bf16.h>
#include <math_constants.h>

// Problem constants
#define BATCH 4
#define SEQ   2048
#define DIM   1024

// GEMM tiling: 128x64 block tile, 8x4 microtile, K-pair (f32x2) accumulation
#define BM 128
#define BN 64
#define BK 16
#define KK2 (BK / 2)   // 8 k-pairs per tile

typedef unsigned long long ull;

// Packed fp32x2 FMA: d.lo += a.lo*b.lo ; d.hi += a.hi*b.hi
#define FFMA2(d, a, b) \
    asm("fma.rn.f32x2 %0, %1, %2, %0;" : "+l"(d) : "l"(a), "l"(b))

__device__ __forceinline__ float pairsum(ull v) {
    float lo = __uint_as_float((unsigned)(v & 0xffffffffu));
    float hi = __uint_as_float((unsigned)(v >> 32));
    return lo + hi;
}

// Scratch
__device__ float g_Q[(long)BATCH * SEQ * DIM];
__device__ float g_K[(long)BATCH * SEQ * DIM];
__device__ float g_V[(long)BATCH * SEQ * DIM];
__device__ float g_S[(long)BATCH * SEQ * SEQ];

// C[M,N] = alpha * A[M,K] @ op(B)
//  TRANSB=true : op(B)=B^T, B stored [N,K] row-major (NT)
//  TRANSB=false: op(B)=B,   B stored [K,N] row-major (NN)
// CAUSAL: 0 none; 1 skip blocks fully above diagonal (scores);
//         2 limit k-loop to (by+1)*BM (P@V with causal-zeroed P)
template<bool TRANSB, int CAUSAL>
__global__ __launch_bounds__(256, 2)
void gemm_kernel(const float* __restrict__ A, const float* __restrict__ B,
                 float* __restrict__ C,
                 int M, int N, int K,
                 long strideA, long strideB, long strideC,
                 float alpha)
{
    if (CAUSAL == 1 && (int)blockIdx.x >= 2 * ((int)blockIdx.y + 1)) return;

    // k-pair-major layout: As[buf][k2][2*m + e] = A[m][2*k2 + e]
    __shared__ float As[2][KK2][2 * BM];   // 2 x 8KB
    __shared__ float Bs[2][KK2][2 * BN];   // 2 x 4KB

    A += (long)blockIdx.z * strideA;
    B += (long)blockIdx.z * strideB;
    C += (long)blockIdx.z * strideC;

    const int tid = threadIdx.x;           // 0..255
    const int tx  = tid & 15;              // col group
    const int ty  = tid >> 4;              // row group
    const int ty4 = ty << 2;               // row chunk base (0..60)
    const int tx2 = tx << 1;               // col chunk base (0..30)
    const int row0 = blockIdx.y * BM;
    const int col0 = blockIdx.x * BN;

    // A loader: thread -> (m = tid/4 and +64, k4 = (tid%4)*4), float4 along k
    const int am = tid >> 2;               // 0..63
    const int ak = (tid & 3) << 2;         // 0,4,8,12
    const long aoff0 = (long)(row0 + am) * K + ak;
    const long aoff1 = aoff0 + (long)64 * K;

    // NN B loader: thread -> (kr = tid/16, n4 = (tid%16)*4), float4 along n
    const int kr = tid >> 4;               // 0..15
    const int n4 = (tid & 15) << 2;        // 0..60

    int kEnd = K;
    if (CAUSAL == 2) {
        int lim = ((int)blockIdx.y + 1) * BM;
        if (lim < kEnd) kEnd = lim;
    }
    const int nT = kEnd / BK;

    ull acc[8][4];
    #pragma unroll
    for (int r = 0; r < 8; r++)
        #pragma unroll
        for (int c = 0; c < 4; c++) acc[r][c] = 0ULL;

    float4 ra0, ra1, rb0, rb1;

    // ---- tile load (gmem -> regs) ----
    auto LDG = [&](int k0) {
        ra0 = *reinterpret_cast<const float4*>(A + aoff0 + k0);
        ra1 = *reinterpret_cast<const float4*>(A + aoff1 + k0);
        if (TRANSB) {
            // B [N,K], BN=64 rows x 16 k = 1 float4/thread (reuse am/ak mapping on first 64)
            rb0 = *reinterpret_cast<const float4*>(B + (long)(col0 + am) * K + k0 + ak);
        } else {
            // B [K,N], 16 k x 64 n = 1 float4/thread
            rb0 = *reinterpret_cast<const float4*>(B + (long)(k0 + kr) * N + col0 + n4);
        }
        (void)rb1;
    };

    // ---- regs -> smem (k-pair layout) ----
    auto STS = [&](int buf) {
        *reinterpret_cast<float2*>(&As[buf][(ak >> 1) + 0][2 * am])        = make_float2(ra0.x, ra0.y);
        *reinterpret_cast<float2*>(&As[buf][(ak >> 1) + 1][2 * am])        = make_float2(ra0.z, ra0.w);
        *reinterpret_cast<float2*>(&As[buf][(ak >> 1) + 0][2 * (am + 64)]) = make_float2(ra1.x, ra1.y);
        *reinterpret_cast<float2*>(&As[buf][(ak >> 1) + 1][2 * (am + 64)]) = make_float2(ra1.z, ra1.w);
        if (TRANSB) {
            *reinterpret_cast<float2*>(&Bs[buf][(ak >> 1) + 0][2 * am]) = make_float2(rb0.x, rb0.y);
            *reinterpret_cast<float2*>(&Bs[buf][(ak >> 1) + 1][2 * am]) = make_float2(rb0.z, rb0.w);
        } else {
            float* bp = &Bs[buf][kr >> 1][kr & 1];
            bp[2 * (n4 + 0)] = rb0.x;
            bp[2 * (n4 + 1)] = rb0.y;
            bp[2 * (n4 + 2)] = rb0.z;
            bp[2 * (n4 + 3)] = rb0.w;
        }
    };

    // ---- compute one tile from smem ----
    auto COMPUTE = [&](int buf) {
        #pragma unroll
        for (int kk = 0; kk < KK2; kk++) {
            ulonglong2 A0 = *reinterpret_cast<const ulonglong2*>(&As[buf][kk][2 * ty4]);
            ulonglong2 A1 = *reinterpret_cast<const ulonglong2*>(&As[buf][kk][2 * ty4 + 4]);
            ulonglong2 A2 = *reinterpret_cast<const ulonglong2*>(&As[buf][kk][2 * ty4 + 128]);
            ulonglong2 A3 = *reinterpret_cast<const ulonglong2*>(&As[buf][kk][2 * ty4 + 132]);
            ulonglong2 B0 = *reinterpret_cast<const ulonglong2*>(&Bs[buf][kk][2 * tx2]);
            ulonglong2 B1 = *reinterpret_cast<const ulonglong2*>(&Bs[buf][kk][2 * tx2 + 64]);
            ull a[8] = {A0.x, A0.y, A1.x, A1.y, A2.x, A2.y, A3.x, A3.y};
            ull b[4] = {B0.x, B0.y, B1.x, B1.y};
            #pragma unroll
            for (int r = 0; r < 8; r++)
                #pragma unroll
                for (int c = 0; c < 4; c++)
                    FFMA2(acc[r][c], a[r], b[c]);
        }
    };

    LDG(0);
    STS(0);
    __syncthreads();

    for (int t = 0; t < nT; t++) {
        int cur = t & 1;
        if (t + 1 < nT) LDG((t + 1) * BK);
        COMPUTE(cur);
        if (t + 1 < nT) {
            STS(cur ^ 1);
            __syncthreads();
        }
    }

    // ---- epilogue: lo+hi reduction, float2 coalesced stores ----
    #pragma unroll
    for (int r = 0; r < 8; r++) {
        int row = row0 + ((r < 4) ? (ty4 + r) : (64 + ty4 + r - 4));
        float2 o0 = make_float2(pairsum(acc[r][0]) * alpha, pairsum(acc[r][1]) * alpha);
        float2 o1 = make_float2(pairsum(acc[r][2]) * alpha, pairsum(acc[r][3]) * alpha);
        *reinterpret_cast<float2*>(&C[(long)row * N + col0 + tx2])      = o0;
        *reinterpret_cast<float2*>(&C[(long)row * N + col0 + 32 + tx2]) = o1;
    }
}

// Row-wise causal + pad-masked softmax, in-place. grid=(S,B), block=256
__global__ __launch_bounds__(256)
void softmax_kernel(float* __restrict__ Sc, const int* __restrict__ mask, int S)
{
    const int q = blockIdx.x;
    const int b = blockIdx.y;
    float* row = Sc + ((long)b * S + q) * (long)S;
    const int* mk = mask + (long)b * S;

    __shared__ float red[256];
    const int tid = threadIdx.x;

    float mx = -CUDART_INF_F;
    for (int c = tid; c <= q; c += 256)
        if (mk[c]) mx = fmaxf(mx, row[c]);
    red[tid] = mx;
    __syncthreads();
    #pragma unroll
    for (int s = 128; s > 0; s >>= 1) {
        if (tid < s) red[tid] = fmaxf(red[tid], red[tid + s]);
        __syncthreads();
    }
    mx = red[0];
    __syncthreads();

    float sum = 0.f;
    for (int c = tid; c <= q; c += 256) {
        float e = mk[c] ? __expf(row[c] - mx) : 0.f;
        row[c] = e;
        sum += e;
    }
    red[tid] = sum;
    __syncthreads();
    #pragma unroll
    for (int s = 128; s > 0; s >>= 1) {
        if (tid < s) red[tid] += red[tid + s];
        __syncthreads();
    }
    const float inv = 1.f / red[0];
    __syncthreads();

    for (int c = tid; c < S; c += 256)
        row[c] = (c <= q) ? row[c] * inv : 0.f;
}

extern "C" void kernel_launch(void* const* d_in, const int* in_sizes, int n_in,
                              void* d_out, int out_size)
{
    const float* x    = (const float*)d_in[0];  // [B, S, D]
    const int*   mask = (const int*)  d_in[1];  // [B, S]
    const float* Wq   = (const float*)d_in[2];  // [D, D]
    const float* Wk   = (const float*)d_in[3];
    const float* Wv   = (const float*)d_in[4];
    float* out = (float*)d_out;                 // [B, S, D]

    float *qp, *kp, *vp, *sp;
    cudaGetSymbolAddress((void**)&qp, g_Q);
    cudaGetSymbolAddress((void**)&kp, g_K);
    cudaGetSymbolAddress((void**)&vp, g_V);
    cudaGetSymbolAddress((void**)&sp, g_S);

    const int  BS = BATCH * SEQ;                // 8192
    const long SQ = (long)SEQ * DIM;
    const long SS = (long)SEQ * SEQ;
    const float scale = 1.0f / 32.0f;           // 1/sqrt(1024)

    dim3 blk(256);

    // QKV projections: [8192,1024] = x @ W^T (NT)
    dim3 gQKV(DIM / BN, BS / BM, 1);            // (16, 64)
    gemm_kernel<true, 0><<<gQKV, blk>>>(x, Wq, qp, BS, DIM, DIM, 0, 0, 0, 1.f);
    gemm_kernel<true, 0><<<gQKV, blk>>>(x, Wk, kp, BS, DIM, DIM, 0, 0, 0, 1.f);
    gemm_kernel<true, 0><<<gQKV, blk>>>(x, Wv, vp, BS, DIM, DIM, 0, 0, 0, 1.f);

    // Scores: per batch S = scale * Q @ K^T (NT, causal block skip)
    dim3 gSC(SEQ / BN, SEQ / BM, BATCH);        // (32, 16, 4)
    gemm_kernel<true, 1><<<gSC, blk>>>(qp, kp, sp, SEQ, SEQ, DIM, SQ, SQ, SS, scale);

    // Softmax
    softmax_kernel<<<dim3(SEQ, BATCH), 256>>>(sp, mask, SEQ);

    // Output: per batch O = P @ V (NN, causal-limited k-loop)
    dim3 gPV(DIM / BN, SEQ / BM, BATCH);        // (16, 16, 4)
    gemm_kernel<false, 2><<<gPV, blk>>>(sp, vp, out, SEQ, DIM, SEQ, SS, SQ, SQ, 1.f);
}

// round 4
// speedup vs baseline: 2.1946x; 1.7310x over previous
#include <cuda_runtime.h>
#include <cuda_bf16.h>
#include <math_constants.h>
#include <cstdint>

#define BATCH 4
#define SEQ   2048
#define DIM   1024
#define K3P   (3 * DIM)   // 3072
#define K3S   (3 * SEQ)   // 6144

#define BM 128
#define BN 128
#define BK 32
#define THREADS 256

// ---------------- scratch ----------------
__device__ __nv_bfloat16 g_x2 [(long)BATCH * SEQ * K3P];   // x  split A-layout (hi,lo,hi)
__device__ __nv_bfloat16 g_Wq2[(long)DIM * K3P];           // W  split B-layout (hi,hi,lo)
__device__ __nv_bfloat16 g_Wk2[(long)DIM * K3P];
__device__ __nv_bfloat16 g_Wv2[(long)DIM * K3P];
__device__ __nv_bfloat16 g_Q2 [(long)BATCH * SEQ * K3P];   // Q  split A-layout
__device__ __nv_bfloat16 g_K2 [(long)BATCH * SEQ * K3P];   // K  split B-layout
__device__ __nv_bfloat16 g_V2 [(long)BATCH * K3S * DIM];   // V  split rows (hi,hi,lo) x [k][n]
__device__ float         g_S  [(long)BATCH * SEQ * SEQ];
__device__ __nv_bfloat16 g_P2 [(long)BATCH * SEQ * K3S];   // P  split A-layout

// ---------------- asm helpers ----------------
__device__ __forceinline__ uint32_t smem_u32(const void* p) {
    uint32_t a;
    asm("{ .reg .u64 t; cvta.to.shared.u64 t, %1; cvt.u32.u64 %0, t; }" : "=r"(a) : "l"(p));
    return a;
}
#define LDMX4(r0,r1,r2,r3,addr) \
    asm volatile("ldmatrix.sync.aligned.m8n8.x4.shared.b16 {%0,%1,%2,%3}, [%4];" \
                 : "=r"(r0),"=r"(r1),"=r"(r2),"=r"(r3) : "r"(addr))
#define LDMX4T(r0,r1,r2,r3,addr) \
    asm volatile("ldmatrix.sync.aligned.m8n8.x4.trans.shared.b16 {%0,%1,%2,%3}, [%4];" \
                 : "=r"(r0),"=r"(r1),"=r"(r2),"=r"(r3) : "r"(addr))
#define MMA(c,a,b0,b1) \
    asm volatile("mma.sync.aligned.m16n8k16.row.col.f32.bf16.bf16.f32 " \
                 "{%0,%1,%2,%3}, {%4,%5,%6,%7}, {%8,%9}, {%0,%1,%2,%3};" \
                 : "+f"((c)[0]),"+f"((c)[1]),"+f"((c)[2]),"+f"((c)[3]) \
                 : "r"((a)[0]),"r"((a)[1]),"r"((a)[2]),"r"((a)[3]),"r"(b0),"r"(b1))
#define CPASYNC(s,g) \
    asm volatile("cp.async.cg.shared.global [%0], [%1], 16;" :: "r"(s),"l"(g))
#define CP_COMMIT() asm volatile("cp.async.commit_group;" ::: "memory")
#define CP_WAIT(N)  asm volatile("cp.async.wait_group %0;" :: "n"(N) : "memory")

__device__ __forceinline__ void split_us(float v, unsigned short& h, unsigned short& l) {
    __nv_bfloat16 hb = __float2bfloat16(v);
    __nv_bfloat16 lb = __float2bfloat16(v - __bfloat162float(hb));
    h = __bfloat16_as_ushort(hb);
    l = __bfloat16_as_ushort(lb);
}

// ---------------- input conversions ----------------
// LAY 0: A-layout (hi,lo,hi)  LAY 1: B-layout (hi,hi,lo)
template<int LAY>
__global__ void convert_kernel(const float* __restrict__ in,
                               __nv_bfloat16* __restrict__ out, long n) {
    long i = (long)blockIdx.x * blockDim.x + threadIdx.x;
    if (i >= n) return;
    unsigned short h, l;
    split_us(in[i], h, l);
    __nv_bfloat16 hb = __ushort_as_bfloat16(h), lb = __ushort_as_bfloat16(l);
    long o = 3 * i;
    if (LAY == 0) { out[o] = hb; out[o+1] = lb; out[o+2] = hb; }
    else          { out[o] = hb; out[o+1] = hb; out[o+2] = lb; }
}

// ---------------- warp-MMA GEMM ----------------
// C[M,N] = alpha * A[M,K3] @ op(B), A K-major bf16 (lda = K3).
//  NT=true : B K-major [n][K3]       NT=false: B row-major [K3][n], ldb cols
// EPI: 0 fp32 (alpha, ldc, batch sC)   1 split A-layout (ldc = 3N)
//      2 split B-layout (ldc = 3N)     3 V2 rows hi,hi,lo (per-batch [K3S][DIM])
// CAUSAL: 0 none; 1 skip bx>by; 2 kEnd = 3*(by+1)*BM
template<bool NT, int EPI, int CAUSAL>
__global__ void __launch_bounds__(THREADS, 2)
mma_gemm(const __nv_bfloat16* __restrict__ A, const __nv_bfloat16* __restrict__ B,
         void* __restrict__ Cout, int K3, int ldb, int ldc,
         long sA, long sB, long sC, float alpha)
{
    if (CAUSAL == 1 && blockIdx.x > blockIdx.y) return;

    __shared__ __nv_bfloat16 As[2][BM][40];   // 20480 B (padded stride 80B)
    __shared__ __nv_bfloat16 Bs[2][BM][40];   // NT layout; NN reuses as [2][32][136]

    const int tid = threadIdx.x, lid = tid & 31, wid = tid >> 5;
    const int wm = wid & 3, wn = wid >> 2;           // warp tile: rows wm*32, cols wn*64
    const int row0 = blockIdx.y * BM, col0 = blockIdx.x * BN;

    A += (long)blockIdx.z * sA;
    B += (long)blockIdx.z * sB;

    int kEnd = K3;
    if (CAUSAL == 2) {
        int lim = 3 * (blockIdx.y + 1) * BM;
        if (lim < kEnd) kEnd = lim;
    }
    const int nT = kEnd / BK;

    const uint32_t sA_ = smem_u32(As);
    const uint32_t sB_ = smem_u32(Bs);

    float acc[2][8][4];
    #pragma unroll
    for (int i = 0; i < 2; i++)
        #pragma unroll
        for (int j = 0; j < 8; j++)
            #pragma unroll
            for (int r = 0; r < 4; r++) acc[i][j][r] = 0.f;

    // ---- async tile load ----
    auto LOAD = [&](int t, int buf) {
        const long kt = (long)t * BK;
        #pragma unroll
        for (int i = 0; i < 2; i++) {
            int idx = tid + i * 256;
            int row = idx >> 2, q = idx & 3;
            CPASYNC(sA_ + (uint32_t)(((buf * BM + row) * 40 + q * 8) * 2),
                    A + (long)(row0 + row) * K3 + kt + q * 8);
            if (NT) {
                CPASYNC(sB_ + (uint32_t)(((buf * BM + row) * 40 + q * 8) * 2),
                        B + (long)(col0 + row) * K3 + kt + q * 8);
            } else {
                int kr = idx >> 4, c = (idx & 15) * 8;
                CPASYNC(sB_ + (uint32_t)(((buf * 32 + kr) * 136 + c) * 2),
                        B + (long)(kt + kr) * ldb + col0 + c);
            }
        }
        CP_COMMIT();
    };

    const int l15 = lid & 15, lh = lid >> 4;

    auto COMPUTE = [&](int buf) {
        #pragma unroll
        for (int ks = 0; ks < 2; ks++) {
            uint32_t a0[4], a1[4];
            uint32_t abase = sA_ + (uint32_t)(((buf * BM + wm * 32 + l15) * 40 + lh * 8 + ks * 16) * 2);
            LDMX4(a0[0], a0[1], a0[2], a0[3], abase);
            LDMX4(a1[0], a1[1], a1[2], a1[3], abase + 16 * 40 * 2);
            #pragma unroll
            for (int j2 = 0; j2 < 4; j2++) {
                uint32_t r0, r1, r2, r3;
                if (NT) {
                    uint32_t baddr = sB_ + (uint32_t)(((buf * BM + wn * 64 + j2 * 16 + l15) * 40 + lh * 8 + ks * 16) * 2);
                    LDMX4(r0, r1, r2, r3, baddr);
                    // r0/r2 = b0/b1 of n-tile 2*j2 ; r1/r3 = of 2*j2+1
                    MMA(acc[0][2*j2],   a0, r0, r2);
                    MMA(acc[1][2*j2],   a1, r0, r2);
                    MMA(acc[0][2*j2+1], a0, r1, r3);
                    MMA(acc[1][2*j2+1], a1, r1, r3);
                } else {
                    uint32_t baddr = sB_ + (uint32_t)(((buf * 32 + ks * 16 + l15) * 136 + wn * 64 + j2 * 16 + lh * 8) * 2);
                    LDMX4T(r0, r1, r2, r3, baddr);
                    // r0/r1 = b0/b1 of n-tile 2*j2 ; r2/r3 = of 2*j2+1
                    MMA(acc[0][2*j2],   a0, r0, r1);
                    MMA(acc[1][2*j2],   a1, r0, r1);
                    MMA(acc[0][2*j2+1], a0, r2, r3);
                    MMA(acc[1][2*j2+1], a1, r2, r3);
                }
            }
        }
    };

    LOAD(0, 0);
    for (int t = 0; t < nT; t++) {
        int buf = t & 1;
        if (t + 1 < nT) { LOAD(t + 1, buf ^ 1); CP_WAIT(1); }
        else            { CP_WAIT(0); }
        __syncthreads();
        COMPUTE(buf);
        __syncthreads();
    }

    // ---- epilogue ----
    const int g = lid >> 2, tig = lid & 3;
    #pragma unroll
    for (int i = 0; i < 2; i++) {
        #pragma unroll
        for (int j = 0; j < 8; j++) {
            const int c = col0 + wn * 64 + j * 8 + 2 * tig;
            #pragma unroll
            for (int s = 0; s < 2; s++) {
                const int r = row0 + wm * 32 + i * 16 + g + s * 8;
                const float v0 = acc[i][j][2*s], v1 = acc[i][j][2*s+1];
                if (EPI == 0) {
                    float* C = (float*)Cout + (long)blockIdx.z * sC;
                    float2 o = make_float2(v0 * alpha, v1 * alpha);
                    *reinterpret_cast<float2*>(&C[(long)r * ldc + c]) = o;
                } else if (EPI == 1 || EPI == 2) {
                    unsigned short h0, l0, h1, l1;
                    split_us(v0, h0, l0);
                    split_us(v1, h1, l1);
                    __nv_bfloat16* C = (__nv_bfloat16*)Cout;
                    uint32_t* p = reinterpret_cast<uint32_t*>(C + (long)r * ldc + 3L * c);
                    if (EPI == 1) {  // hi,lo,hi | hi,lo,hi
                        p[0] = (uint32_t)h0 | ((uint32_t)l0 << 16);
                        p[1] = (uint32_t)h0 | ((uint32_t)h1 << 16);
                        p[2] = (uint32_t)l1 | ((uint32_t)h1 << 16);
                    } else {         // hi,hi,lo | hi,hi,lo
                        p[0] = (uint32_t)h0 | ((uint32_t)h0 << 16);
                        p[1] = (uint32_t)l0 | ((uint32_t)h1 << 16);
                        p[2] = (uint32_t)h1 | ((uint32_t)l1 << 16);
                    }
                } else {  // EPI == 3: V2 rows (hi,hi,lo), M spans batches
                    unsigned short h0, l0, h1, l1;
                    split_us(v0, h0, l0);
                    split_us(v1, h1, l1);
                    const int bz = r >> 11, tok = r & (SEQ - 1);
                    __nv_bfloat16* Vb = (__nv_bfloat16*)Cout + (long)bz * K3S * DIM;
                    uint32_t uh = (uint32_t)h0 | ((uint32_t)h1 << 16);
                    uint32_t ul = (uint32_t)l0 | ((uint32_t)l1 << 16);
                    long rb = (long)(3 * tok) * DIM + c;
                    *reinterpret_cast<uint32_t*>(&Vb[rb])           = uh;
                    *reinterpret_cast<uint32_t*>(&Vb[rb + DIM])     = uh;
                    *reinterpret_cast<uint32_t*>(&Vb[rb + 2 * DIM]) = ul;
                }
            }
        }
    }
}

// ---------------- softmax: fp32 scores -> split-bf16 P (A-layout) ----------------
__global__ __launch_bounds__(256)
void softmax_p2(const float* __restrict__ Sc, const int* __restrict__ mask,
                __nv_bfloat16* __restrict__ P2)
{
    __shared__ float e[SEQ];
    __shared__ float red[256];
    const int q = blockIdx.x, b = blockIdx.y, tid = threadIdx.x;
    const float* row = Sc + ((long)b * SEQ + q) * SEQ;
    const int* mk = mask + (long)b * SEQ;
    __nv_bfloat16* pr = P2 + ((long)b * SEQ + q) * (long)K3S;

    float mx = -CUDART_INF_F;
    for (int c = tid; c <= q; c += 256)
        if (mk[c]) mx = fmaxf(mx, row[c]);
    red[tid] = mx; __syncthreads();
    #pragma unroll
    for (int s = 128; s > 0; s >>= 1) {
        if (tid < s) red[tid] = fmaxf(red[tid], red[tid + s]);
        __syncthreads();
    }
    mx = red[0]; __syncthreads();

    float sum = 0.f;
    for (int c = tid; c <= q; c += 256) {
        float v = mk[c] ? __expf(row[c] - mx) : 0.f;
        e[c] = v; sum += v;
    }
    red[tid] = sum; __syncthreads();
    #pragma unroll
    for (int s = 128; s > 0; s >>= 1) {
        if (tid < s) red[tid] += red[tid + s];
        __syncthreads();
    }
    const float inv = 1.f / red[0];
    __syncthreads();

    for (int c = tid; c < SEQ; c += 256) {
        float v = (c <= q) ? e[c] * inv : 0.f;
        unsigned short h, l;
        split_us(v, h, l);
        pr[3*c]   = __ushort_as_bfloat16(h);
        pr[3*c+1] = __ushort_as_bfloat16(l);
        pr[3*c+2] = __ushort_as_bfloat16(h);
    }
}

// ---------------- host ----------------
extern "C" void kernel_launch(void* const* d_in, const int* in_sizes, int n_in,
                              void* d_out, int out_size)
{
    const float* x    = (const float*)d_in[0];
    const int*   mask = (const int*)  d_in[1];
    const float* Wq   = (const float*)d_in[2];
    const float* Wk   = (const float*)d_in[3];
    const float* Wv   = (const float*)d_in[4];
    float* out = (float*)d_out;

    __nv_bfloat16 *x2p, *wq2, *wk2, *wv2, *q2p, *k2p, *v2p, *p2p;
    float* sp;
    cudaGetSymbolAddress((void**)&x2p, g_x2);
    cudaGetSymbolAddress((void**)&wq2, g_Wq2);
    cudaGetSymbolAddress((void**)&wk2, g_Wk2);
    cudaGetSymbolAddress((void**)&wv2, g_Wv2);
    cudaGetSymbolAddress((void**)&q2p, g_Q2);
    cudaGetSymbolAddress((void**)&k2p, g_K2);
    cudaGetSymbolAddress((void**)&v2p, g_V2);
    cudaGetSymbolAddress((void**)&sp,  g_S);
    cudaGetSymbolAddress((void**)&p2p, g_P2);

    const long nx = (long)BATCH * SEQ * DIM;
    const long nw = (long)DIM * DIM;
    convert_kernel<0><<<(unsigned)((nx + 255) / 256), 256>>>(x,  x2p, nx);
    convert_kernel<1><<<(unsigned)((nw + 255) / 256), 256>>>(Wq, wq2, nw);
    convert_kernel<1><<<(unsigned)((nw + 255) / 256), 256>>>(Wk, wk2, nw);
    convert_kernel<1><<<(unsigned)((nw + 255) / 256), 256>>>(Wv, wv2, nw);

    const long SQ3 = (long)SEQ * K3P;
    const long SS  = (long)SEQ * SEQ;

    // projections: [8192 x 1024], K3 = 3072 (NT)
    dim3 gP(DIM / BN, (BATCH * SEQ) / BM, 1);            // (8, 64)
    mma_gemm<true, 1, 0><<<gP, THREADS>>>(x2p, wq2, q2p, K3P, 0, K3P, 0, 0, 0, 1.f);
    mma_gemm<true, 2, 0><<<gP, THREADS>>>(x2p, wk2, k2p, K3P, 0, K3P, 0, 0, 0, 1.f);
    mma_gemm<true, 3, 0><<<gP, THREADS>>>(x2p, wv2, v2p, K3P, 0, 0,   0, 0, 0, 1.f);

    // scores: per batch, causal block skip (NT)
    dim3 gS(SEQ / BN, SEQ / BM, BATCH);                  // (16, 16, 4)
    mma_gemm<true, 0, 1><<<gS, THREADS>>>(q2p, k2p, sp, K3P, 0, SEQ, SQ3, SQ3, SS, 1.f / 32.f);

    // softmax -> split P
    softmax_p2<<<dim3(SEQ, BATCH), 256>>>(sp, mask, p2p);

    // O = P @ V : NN with causal k-limit
    dim3 gO(DIM / BN, SEQ / BM, BATCH);                  // (8, 16, 4)
    mma_gemm<false, 0, 2><<<gO, THREADS>>>(p2p, v2p, out, K3S, DIM, DIM,
                                           (long)SEQ * K3S, (long)K3S * DIM,
                                           (long)SEQ * DIM, 1.f);
}

// round 5
// speedup vs baseline: 2.5028x; 1.1404x over previous
#include <cuda_runtime.h>
#include <cuda_bf16.h>
#include <math_constants.h>
#include <cstdint>

#define BATCH 4
#define SEQ   2048
#define DIM   1024
#define K3P   (3 * DIM)   // 3072
#define K3S   (3 * SEQ)   // 6144

#define BM 128
#define BN 128
#define BK 32
#define THREADS 256
#define STAGES 4
#define A_STAGE_BYTES 10240u           // 128 rows x 40 elems x 2B
#define STAGE_BYTES   20480u           // A + B region per stage
#define SMEM_TOTAL (STAGES * STAGE_BYTES)   // 81920

// ---------------- scratch ----------------
__device__ __nv_bfloat16 g_x2 [(long)BATCH * SEQ * K3P];   // x  split A-layout (hi,lo,hi)
__device__ __nv_bfloat16 g_Wq2[(long)DIM * K3P];           // W  split B-layout (hi,hi,lo)
__device__ __nv_bfloat16 g_Wk2[(long)DIM * K3P];
__device__ __nv_bfloat16 g_Wv2[(long)DIM * K3P];
__device__ __nv_bfloat16 g_Q2 [(long)BATCH * SEQ * K3P];   // Q  split A-layout
__device__ __nv_bfloat16 g_K2 [(long)BATCH * SEQ * K3P];   // K  split B-layout
__device__ __nv_bfloat16 g_V2 [(long)BATCH * K3S * DIM];   // V  split rows (hi,hi,lo) x [k][n]
__device__ float         g_S  [(long)BATCH * SEQ * SEQ];
__device__ __nv_bfloat16 g_P2 [(long)BATCH * SEQ * K3S];   // P  split A-layout

// ---------------- asm helpers ----------------
__device__ __forceinline__ uint32_t smem_u32(const void* p) {
    uint32_t a;
    asm("{ .reg .u64 t; cvta.to.shared.u64 t, %1; cvt.u32.u64 %0, t; }" : "=r"(a) : "l"(p));
    return a;
}
#define LDMX4(r0,r1,r2,r3,addr) \
    asm volatile("ldmatrix.sync.aligned.m8n8.x4.shared.b16 {%0,%1,%2,%3}, [%4];" \
                 : "=r"(r0),"=r"(r1),"=r"(r2),"=r"(r3) : "r"(addr))
#define LDMX4T(r0,r1,r2,r3,addr) \
    asm volatile("ldmatrix.sync.aligned.m8n8.x4.trans.shared.b16 {%0,%1,%2,%3}, [%4];" \
                 : "=r"(r0),"=r"(r1),"=r"(r2),"=r"(r3) : "r"(addr))
#define MMA(c,a,b0,b1) \
    asm volatile("mma.sync.aligned.m16n8k16.row.col.f32.bf16.bf16.f32 " \
                 "{%0,%1,%2,%3}, {%4,%5,%6,%7}, {%8,%9}, {%0,%1,%2,%3};" \
                 : "+f"((c)[0]),"+f"((c)[1]),"+f"((c)[2]),"+f"((c)[3]) \
                 : "r"((a)[0]),"r"((a)[1]),"r"((a)[2]),"r"((a)[3]),"r"(b0),"r"(b1))
#define CPASYNC(s,g) \
    asm volatile("cp.async.cg.shared.global [%0], [%1], 16;" :: "r"(s),"l"(g))
#define CP_COMMIT() asm volatile("cp.async.commit_group;" ::: "memory")
#define CP_WAIT(N)  asm volatile("cp.async.wait_group %0;" :: "n"(N) : "memory")

__device__ __forceinline__ void split_us(float v, unsigned short& h, unsigned short& l) {
    __nv_bfloat16 hb = __float2bfloat16(v);
    __nv_bfloat16 lb = __float2bfloat16(v - __bfloat162float(hb));
    h = __bfloat16_as_ushort(hb);
    l = __bfloat16_as_ushort(lb);
}

// ---------------- input conversions (vectorized) ----------------
// LAY 0: A-layout (hi,lo,hi)  LAY 1: B-layout (hi,hi,lo)
template<int LAY>
__global__ void convert_kernel(const float4* __restrict__ in,
                               uint2* __restrict__ out, long n4) {
    long i = (long)blockIdx.x * blockDim.x + threadIdx.x;
    if (i >= n4) return;
    float4 v = in[i];
    unsigned short h[4], l[4];
    split_us(v.x, h[0], l[0]);
    split_us(v.y, h[1], l[1]);
    split_us(v.z, h[2], l[2]);
    split_us(v.w, h[3], l[3]);
    unsigned short t[12];
    #pragma unroll
    for (int e = 0; e < 4; e++) {
        if (LAY == 0) { t[3*e] = h[e]; t[3*e+1] = l[e]; t[3*e+2] = h[e]; }
        else          { t[3*e] = h[e]; t[3*e+1] = h[e]; t[3*e+2] = l[e]; }
    }
    uint2* o = out + 3 * i;
    #pragma unroll
    for (int j = 0; j < 3; j++) {
        uint2 u;
        u.x = (uint32_t)t[4*j]   | ((uint32_t)t[4*j+1] << 16);
        u.y = (uint32_t)t[4*j+2] | ((uint32_t)t[4*j+3] << 16);
        o[j] = u;
    }
}

// ---------------- warp-MMA GEMM (4-stage cp.async ring) ----------------
// C[M,N] = alpha * A[M,K3] @ op(B), A K-major bf16 (lda = K3).
//  NT=true : B K-major [n][K3]       NT=false: B row-major [K3][n], ldb cols
// EPI: 0 fp32 (alpha, ldc, batch sC)   1 split A-layout (ldc = 3N)
//      2 split B-layout (ldc = 3N)     3 V2 rows hi,hi,lo (per-batch [K3S][DIM])
// CAUSAL: 0 none; 1 skip bx>by; 2 kEnd = 3*(by+1)*BM
template<bool NT, int EPI, int CAUSAL>
__global__ void __launch_bounds__(THREADS, 2)
mma_gemm(const __nv_bfloat16* __restrict__ A, const __nv_bfloat16* __restrict__ B,
         void* __restrict__ Cout, int K3, int ldb, int ldc,
         long sA, long sB, long sC, float alpha)
{
    if (CAUSAL == 1 && blockIdx.x > blockIdx.y) return;

    extern __shared__ char smem[];
    const uint32_t sbase = smem_u32(smem);

    const int tid = threadIdx.x, lid = tid & 31, wid = tid >> 5;
    const int wm = wid & 3, wn = wid >> 2;           // warp tile: rows wm*32, cols wn*64
    const int row0 = blockIdx.y * BM, col0 = blockIdx.x * BN;

    A += (long)blockIdx.z * sA;
    B += (long)blockIdx.z * sB;

    int kEnd = K3;
    if (CAUSAL == 2) {
        int lim = 3 * (blockIdx.y + 1) * BM;
        if (lim < kEnd) kEnd = lim;
    }
    const int nT = kEnd / BK;

    float acc[2][8][4];
    #pragma unroll
    for (int i = 0; i < 2; i++)
        #pragma unroll
        for (int j = 0; j < 8; j++)
            #pragma unroll
            for (int r = 0; r < 4; r++) acc[i][j][r] = 0.f;

    // ---- async tile load into ring stage ----
    auto LOAD = [&](int t, int st) {
        const long kt = (long)t * BK;
        const uint32_t aoff = sbase + (uint32_t)st * STAGE_BYTES;
        const uint32_t boff = aoff + A_STAGE_BYTES;
        #pragma unroll
        for (int i = 0; i < 2; i++) {
            int idx = tid + i * 256;
            int row = idx >> 2, q = idx & 3;
            CPASYNC(aoff + (uint32_t)((row * 40 + q * 8) * 2),
                    A + (long)(row0 + row) * K3 + kt + q * 8);
            if (NT) {
                CPASYNC(boff + (uint32_t)((row * 40 + q * 8) * 2),
                        B + (long)(col0 + row) * K3 + kt + q * 8);
            } else {
                int kr = idx >> 4, c = (idx & 15) * 8;
                CPASYNC(boff + (uint32_t)((kr * 136 + c) * 2),
                        B + (long)(kt + kr) * ldb + col0 + c);
            }
        }
        CP_COMMIT();
    };

    const int l15 = lid & 15, lh = lid >> 4;

    auto COMPUTE = [&](int st) {
        const uint32_t aoff = sbase + (uint32_t)st * STAGE_BYTES;
        const uint32_t boff = aoff + A_STAGE_BYTES;
        #pragma unroll
        for (int ks = 0; ks < 2; ks++) {
            uint32_t a0[4], a1[4];
            uint32_t abase = aoff + (uint32_t)(((wm * 32 + l15) * 40 + lh * 8 + ks * 16) * 2);
            LDMX4(a0[0], a0[1], a0[2], a0[3], abase);
            LDMX4(a1[0], a1[1], a1[2], a1[3], abase + 16 * 40 * 2);
            #pragma unroll
            for (int j2 = 0; j2 < 4; j2++) {
                uint32_t r0, r1, r2, r3;
                if (NT) {
                    uint32_t baddr = boff + (uint32_t)(((wn * 64 + j2 * 16 + l15) * 40 + lh * 8 + ks * 16) * 2);
                    LDMX4(r0, r1, r2, r3, baddr);
                    MMA(acc[0][2*j2],   a0, r0, r2);
                    MMA(acc[1][2*j2],   a1, r0, r2);
                    MMA(acc[0][2*j2+1], a0, r1, r3);
                    MMA(acc[1][2*j2+1], a1, r1, r3);
                } else {
                    uint32_t baddr = boff + (uint32_t)(((ks * 16 + l15) * 136 + wn * 64 + j2 * 16 + lh * 8) * 2);
                    LDMX4T(r0, r1, r2, r3, baddr);
                    MMA(acc[0][2*j2],   a0, r0, r1);
                    MMA(acc[1][2*j2],   a1, r0, r1);
                    MMA(acc[0][2*j2+1], a0, r2, r3);
                    MMA(acc[1][2*j2+1], a1, r2, r3);
                }
            }
        }
    };

    // prologue: fill STAGES-1 stages (nT >= 12 always)
    #pragma unroll
    for (int s = 0; s < STAGES - 1; s++) LOAD(s, s);

    for (int t = 0; t < nT; t++) {
        CP_WAIT(STAGES - 2);        // tile t's stage has landed
        __syncthreads();
        COMPUTE(t & (STAGES - 1));
        int nt = t + STAGES - 1;
        if (nt < nT) LOAD(nt, nt & (STAGES - 1));
        else         CP_COMMIT();   // keep group counting aligned
    }

    // ---- epilogue ----
    const int g = lid >> 2, tig = lid & 3;
    #pragma unroll
    for (int i = 0; i < 2; i++) {
        #pragma unroll
        for (int j = 0; j < 8; j++) {
            const int c = col0 + wn * 64 + j * 8 + 2 * tig;
            #pragma unroll
            for (int s = 0; s < 2; s++) {
                const int r = row0 + wm * 32 + i * 16 + g + s * 8;
                const float v0 = acc[i][j][2*s], v1 = acc[i][j][2*s+1];
                if (EPI == 0) {
                    float* C = (float*)Cout + (long)blockIdx.z * sC;
                    float2 o = make_float2(v0 * alpha, v1 * alpha);
                    *reinterpret_cast<float2*>(&C[(long)r * ldc + c]) = o;
                } else if (EPI == 1 || EPI == 2) {
                    unsigned short h0, l0, h1, l1;
                    split_us(v0, h0, l0);
                    split_us(v1, h1, l1);
                    __nv_bfloat16* C = (__nv_bfloat16*)Cout;
                    uint32_t* p = reinterpret_cast<uint32_t*>(C + (long)r * ldc + 3L * c);
                    if (EPI == 1) {  // hi,lo,hi | hi,lo,hi
                        p[0] = (uint32_t)h0 | ((uint32_t)l0 << 16);
                        p[1] = (uint32_t)h0 | ((uint32_t)h1 << 16);
                        p[2] = (uint32_t)l1 | ((uint32_t)h1 << 16);
                    } else {         // hi,hi,lo | hi,hi,lo
                        p[0] = (uint32_t)h0 | ((uint32_t)h0 << 16);
                        p[1] = (uint32_t)l0 | ((uint32_t)h1 << 16);
                        p[2] = (uint32_t)h1 | ((uint32_t)l1 << 16);
                    }
                } else {  // EPI == 3: V2 rows (hi,hi,lo), M spans batches
                    unsigned short h0, l0, h1, l1;
                    split_us(v0, h0, l0);
                    split_us(v1, h1, l1);
                    const int bz = r >> 11, tok = r & (SEQ - 1);
                    __nv_bfloat16* Vb = (__nv_bfloat16*)Cout + (long)bz * K3S * DIM;
                    uint32_t uh = (uint32_t)h0 | ((uint32_t)h1 << 16);
                    uint32_t ul = (uint32_t)l0 | ((uint32_t)l1 << 16);
                    long rb = (long)(3 * tok) * DIM + c;
                    *reinterpret_cast<uint32_t*>(&Vb[rb])           = uh;
                    *reinterpret_cast<uint32_t*>(&Vb[rb + DIM])     = uh;
                    *reinterpret_cast<uint32_t*>(&Vb[rb + 2 * DIM]) = ul;
                }
            }
        }
    }
}

// ---------------- softmax: fp32 scores -> split-bf16 P (A-layout) ----------------
__global__ __launch_bounds__(256)
void softmax_p2(const float* __restrict__ Sc, const int* __restrict__ mask,
                __nv_bfloat16* __restrict__ P2)
{
    __shared__ float e[SEQ];
    __shared__ float red[256];
    const int q = blockIdx.x, b = blockIdx.y, tid = threadIdx.x;
    const float* row = Sc + ((long)b * SEQ + q) * SEQ;
    const int* mk = mask + (long)b * SEQ;
    __nv_bfloat16* pr = P2 + ((long)b * SEQ + q) * (long)K3S;

    float mx = -CUDART_INF_F;
    for (int c = tid; c <= q; c += 256)
        if (mk[c]) mx = fmaxf(mx, row[c]);
    red[tid] = mx; __syncthreads();
    #pragma unroll
    for (int s = 128; s > 0; s >>= 1) {
        if (tid < s) red[tid] = fmaxf(red[tid], red[tid + s]);
        __syncthreads();
    }
    mx = red[0]; __syncthreads();

    float sum = 0.f;
    for (int c = tid; c <= q; c += 256) {
        float v = mk[c] ? __expf(row[c] - mx) : 0.f;
        e[c] = v; sum += v;
    }
    red[tid] = sum; __syncthreads();
    #pragma unroll
    for (int s = 128; s > 0; s >>= 1) {
        if (tid < s) red[tid] += red[tid + s];
        __syncthreads();
    }
    const float inv = 1.f / red[0];
    __syncthreads();

    for (int c = tid; c < SEQ; c += 256) {
        float v = (c <= q) ? e[c] * inv : 0.f;
        unsigned short h, l;
        split_us(v, h, l);
        pr[3*c]   = __ushort_as_bfloat16(h);
        pr[3*c+1] = __ushort_as_bfloat16(l);
        pr[3*c+2] = __ushort_as_bfloat16(h);
    }
}

// ---------------- host ----------------
extern "C" void kernel_launch(void* const* d_in, const int* in_sizes, int n_in,
                              void* d_out, int out_size)
{
    const float* x    = (const float*)d_in[0];
    const int*   mask = (const int*)  d_in[1];
    const float* Wq   = (const float*)d_in[2];
    const float* Wk   = (const float*)d_in[3];
    const float* Wv   = (const float*)d_in[4];
    float* out = (float*)d_out;

    __nv_bfloat16 *x2p, *wq2, *wk2, *wv2, *q2p, *k2p, *v2p, *p2p;
    float* sp;
    cudaGetSymbolAddress((void**)&x2p, g_x2);
    cudaGetSymbolAddress((void**)&wq2, g_Wq2);
    cudaGetSymbolAddress((void**)&wk2, g_Wk2);
    cudaGetSymbolAddress((void**)&wv2, g_Wv2);
    cudaGetSymbolAddress((void**)&q2p, g_Q2);
    cudaGetSymbolAddress((void**)&k2p, g_K2);
    cudaGetSymbolAddress((void**)&v2p, g_V2);
    cudaGetSymbolAddress((void**)&sp,  g_S);
    cudaGetSymbolAddress((void**)&p2p, g_P2);

    static bool attr_done = false;
    if (!attr_done) {
        cudaFuncSetAttribute(mma_gemm<true, 1, 0>, cudaFuncAttributeMaxDynamicSharedMemorySize, SMEM_TOTAL);
        cudaFuncSetAttribute(mma_gemm<true, 2, 0>, cudaFuncAttributeMaxDynamicSharedMemorySize, SMEM_TOTAL);
        cudaFuncSetAttribute(mma_gemm<true, 3, 0>, cudaFuncAttributeMaxDynamicSharedMemorySize, SMEM_TOTAL);
        cudaFuncSetAttribute(mma_gemm<true, 0, 1>, cudaFuncAttributeMaxDynamicSharedMemorySize, SMEM_TOTAL);
        cudaFuncSetAttribute(mma_gemm<false, 0, 2>, cudaFuncAttributeMaxDynamicSharedMemorySize, SMEM_TOTAL);
        attr_done = true;
    }

    const long nx4 = (long)BATCH * SEQ * DIM / 4;
    const long nw4 = (long)DIM * DIM / 4;
    convert_kernel<0><<<(unsigned)((nx4 + 255) / 256), 256>>>((const float4*)x,  (uint2*)x2p, nx4);
    convert_kernel<1><<<(unsigned)((nw4 + 255) / 256), 256>>>((const float4*)Wq, (uint2*)wq2, nw4);
    convert_kernel<1><<<(unsigned)((nw4 + 255) / 256), 256>>>((const float4*)Wk, (uint2*)wk2, nw4);
    convert_kernel<1><<<(unsigned)((nw4 + 255) / 256), 256>>>((const float4*)Wv, (uint2*)wv2, nw4);

    const long SQ3 = (long)SEQ * K3P;
    const long SS  = (long)SEQ * SEQ;

    // projections: [8192 x 1024], K3 = 3072 (NT)
    dim3 gP(DIM / BN, (BATCH * SEQ) / BM, 1);            // (8, 64)
    mma_gemm<true, 1, 0><<<gP, THREADS, SMEM_TOTAL>>>(x2p, wq2, q2p, K3P, 0, K3P, 0, 0, 0, 1.f);
    mma_gemm<true, 2, 0><<<gP, THREADS, SMEM_TOTAL>>>(x2p, wk2, k2p, K3P, 0, K3P, 0, 0, 0, 1.f);
    mma_gemm<true, 3, 0><<<gP, THREADS, SMEM_TOTAL>>>(x2p, wv2, v2p, K3P, 0, 0,   0, 0, 0, 1.f);

    // scores: per batch, causal block skip (NT)
    dim3 gS(SEQ / BN, SEQ / BM, BATCH);                  // (16, 16, 4)
    mma_gemm<true, 0, 1><<<gS, THREADS, SMEM_TOTAL>>>(q2p, k2p, sp, K3P, 0, SEQ, SQ3, SQ3, SS, 1.f / 32.f);

    // softmax -> split P
    softmax_p2<<<dim3(SEQ, BATCH), 256>>>(sp, mask, p2p);

    // O = P @ V : NN with causal k-limit
    dim3 gO(DIM / BN, SEQ / BM, BATCH);                  // (8, 16, 4)
    mma_gemm<false, 0, 2><<<gO, THREADS, SMEM_TOTAL>>>(p2p, v2p, out, K3S, DIM, DIM,
                                                       (long)SEQ * K3S, (long)K3S * DIM,
                                                       (long)SEQ * DIM, 1.f);
}

// round 6
// speedup vs baseline: 2.7950x; 1.1168x over previous
#include <cuda_runtime.h>
#include <cuda_bf16.h>
#include <math_constants.h>
#include <cstdint>

#define BATCH 4
#define SEQ   2048
#define DIM   1024
#define K3P   (3 * DIM)   // 3072
#define K3S   (3 * SEQ)   // 6144

#define BM 128
#define BN 128
#define BK 32
#define THREADS 256
#define STAGES 4
#define A_STAGE_BYTES 10240u           // 128 rows x 40 elems x 2B
#define STAGE_BYTES   20480u           // A + B region per stage
#define SMEM_TOTAL (STAGES * STAGE_BYTES)   // 81920

// ---------------- scratch ----------------
__device__ __nv_bfloat16 g_x2 [(long)BATCH * SEQ * K3P];   // x  split A-layout (hi,lo,hi)
__device__ __nv_bfloat16 g_Wq2[(long)DIM * K3P];           // W  split B-layout (hi,hi,lo)
__device__ __nv_bfloat16 g_Wk2[(long)DIM * K3P];
__device__ __nv_bfloat16 g_Wv2[(long)DIM * K3P];
__device__ __nv_bfloat16 g_Q2 [(long)BATCH * SEQ * K3P];   // Q  split A-layout
__device__ __nv_bfloat16 g_K2 [(long)BATCH * SEQ * K3P];   // K  split B-layout
__device__ __nv_bfloat16 g_V2 [(long)BATCH * K3S * DIM];   // V  split rows (hi,hi,lo) x [k][n]
__device__ float         g_S  [(long)BATCH * SEQ * SEQ];
__device__ __nv_bfloat16 g_P2 [(long)BATCH * SEQ * K3S];   // P  split A-layout

// ---------------- asm helpers ----------------
__device__ __forceinline__ uint32_t smem_u32(const void* p) {
    uint32_t a;
    asm("{ .reg .u64 t; cvta.to.shared.u64 t, %1; cvt.u32.u64 %0, t; }" : "=r"(a) : "l"(p));
    return a;
}
#define LDMX4(r0,r1,r2,r3,addr) \
    asm volatile("ldmatrix.sync.aligned.m8n8.x4.shared.b16 {%0,%1,%2,%3}, [%4];" \
                 : "=r"(r0),"=r"(r1),"=r"(r2),"=r"(r3) : "r"(addr))
#define LDMX4T(r0,r1,r2,r3,addr) \
    asm volatile("ldmatrix.sync.aligned.m8n8.x4.trans.shared.b16 {%0,%1,%2,%3}, [%4];" \
                 : "=r"(r0),"=r"(r1),"=r"(r2),"=r"(r3) : "r"(addr))
#define MMA(c,a,b0,b1) \
    asm volatile("mma.sync.aligned.m16n8k16.row.col.f32.bf16.bf16.f32 " \
                 "{%0,%1,%2,%3}, {%4,%5,%6,%7}, {%8,%9}, {%0,%1,%2,%3};" \
                 : "+f"((c)[0]),"+f"((c)[1]),"+f"((c)[2]),"+f"((c)[3]) \
                 : "r"((a)[0]),"r"((a)[1]),"r"((a)[2]),"r"((a)[3]),"r"(b0),"r"(b1))
#define CPASYNC(s,g) \
    asm volatile("cp.async.cg.shared.global [%0], [%1], 16;" :: "r"(s),"l"(g))
#define CP_COMMIT() asm volatile("cp.async.commit_group;" ::: "memory")
#define CP_WAIT(N)  asm volatile("cp.async.wait_group %0;" :: "n"(N) : "memory")

__device__ __forceinline__ void split_us(float v, unsigned short& h, unsigned short& l) {
    __nv_bfloat16 hb = __float2bfloat16(v);
    __nv_bfloat16 lb = __float2bfloat16(v - __bfloat162float(hb));
    h = __bfloat16_as_ushort(hb);
    l = __bfloat16_as_ushort(lb);
}

// ---------------- epilogue helpers ----------------
// EPI 1: split A-layout (hi,lo,hi) pair; EPI 2: split B-layout (hi,hi,lo) pair
__device__ __forceinline__ void store_split_pair(uint32_t* p, float v0, float v1, int lay) {
    unsigned short h0, l0, h1, l1;
    split_us(v0, h0, l0);
    split_us(v1, h1, l1);
    if (lay == 1) {
        p[0] = (uint32_t)h0 | ((uint32_t)l0 << 16);
        p[1] = (uint32_t)h0 | ((uint32_t)h1 << 16);
        p[2] = (uint32_t)l1 | ((uint32_t)h1 << 16);
    } else {
        p[0] = (uint32_t)h0 | ((uint32_t)h0 << 16);
        p[1] = (uint32_t)l0 | ((uint32_t)h1 << 16);
        p[2] = (uint32_t)h1 | ((uint32_t)l1 << 16);
    }
}

// ---------------- input conversions ----------------
// x: A-layout (hi,lo,hi)
__global__ void convert_x(const float4* __restrict__ in, uint2* __restrict__ out, long n4) {
    long i = (long)blockIdx.x * blockDim.x + threadIdx.x;
    if (i >= n4) return;
    float4 v = in[i];
    unsigned short h[4], l[4];
    split_us(v.x, h[0], l[0]); split_us(v.y, h[1], l[1]);
    split_us(v.z, h[2], l[2]); split_us(v.w, h[3], l[3]);
    unsigned short t[12];
    #pragma unroll
    for (int e = 0; e < 4; e++) { t[3*e] = h[e]; t[3*e+1] = l[e]; t[3*e+2] = h[e]; }
    uint2* o = out + 3 * i;
    #pragma unroll
    for (int j = 0; j < 3; j++) {
        uint2 u;
        u.x = (uint32_t)t[4*j]   | ((uint32_t)t[4*j+1] << 16);
        u.y = (uint32_t)t[4*j+2] | ((uint32_t)t[4*j+3] << 16);
        o[j] = u;
    }
}

// all 3 weights in one launch: B-layout (hi,hi,lo); grid.y selects W
__global__ void convert_w(const float4* __restrict__ wq, const float4* __restrict__ wk,
                          const float4* __restrict__ wv,
                          uint2* __restrict__ oq, uint2* __restrict__ ok,
                          uint2* __restrict__ ov, long n4) {
    long i = (long)blockIdx.x * blockDim.x + threadIdx.x;
    if (i >= n4) return;
    const float4* in = (blockIdx.y == 0) ? wq : (blockIdx.y == 1) ? wk : wv;
    uint2* out = (blockIdx.y == 0) ? oq : (blockIdx.y == 1) ? ok : ov;
    float4 v = in[i];
    unsigned short h[4], l[4];
    split_us(v.x, h[0], l[0]); split_us(v.y, h[1], l[1]);
    split_us(v.z, h[2], l[2]); split_us(v.w, h[3], l[3]);
    unsigned short t[12];
    #pragma unroll
    for (int e = 0; e < 4; e++) { t[3*e] = h[e]; t[3*e+1] = h[e]; t[3*e+2] = l[e]; }
    uint2* o = out + 3 * i;
    #pragma unroll
    for (int j = 0; j < 3; j++) {
        uint2 u;
        u.x = (uint32_t)t[4*j]   | ((uint32_t)t[4*j+1] << 16);
        u.y = (uint32_t)t[4*j+2] | ((uint32_t)t[4*j+3] << 16);
        o[j] = u;
    }
}

// ================= shared GEMM machinery =================
struct Frag { uint32_t a[2][2][4]; };   // [ks][rowhalf][4]

__device__ __forceinline__ void load_afrags(Frag& f, uint32_t aoff, int wm, int l15, int lh) {
    #pragma unroll
    for (int ks = 0; ks < 2; ks++) {
        uint32_t abase = aoff + (uint32_t)(((wm * 32 + l15) * 40 + lh * 8 + ks * 16) * 2);
        LDMX4(f.a[ks][0][0], f.a[ks][0][1], f.a[ks][0][2], f.a[ks][0][3], abase);
        LDMX4(f.a[ks][1][0], f.a[ks][1][1], f.a[ks][1][2], f.a[ks][1][3], abase + 16 * 40 * 2);
    }
}

// ---------------- merged QKV projection ----------------
// grid (24, 64): wsel = bx>>3 (0:Q,1:K,2:V), col block = bx&7
__global__ void __launch_bounds__(THREADS, 2)
qkv_gemm(const __nv_bfloat16* __restrict__ A,
         const __nv_bfloat16* __restrict__ Wq, const __nv_bfloat16* __restrict__ Wk,
         const __nv_bfloat16* __restrict__ Wv,
         __nv_bfloat16* __restrict__ Qo, __nv_bfloat16* __restrict__ Ko,
         __nv_bfloat16* __restrict__ Vo)
{
    extern __shared__ char smem[];
    const uint32_t sbase = smem_u32(smem);

    const int wsel = blockIdx.x >> 3;
    const __nv_bfloat16* B = (wsel == 0) ? Wq : (wsel == 1) ? Wk : Wv;

    const int tid = threadIdx.x, lid = tid & 31, wid = tid >> 5;
    const int wm = wid & 3, wn = wid >> 2;
    const int row0 = blockIdx.y * BM, col0 = (blockIdx.x & 7) * BN;
    const int nT = K3P / BK;   // 96

    float acc[2][8][4];
    #pragma unroll
    for (int i = 0; i < 2; i++)
        #pragma unroll
        for (int j = 0; j < 8; j++)
            #pragma unroll
            for (int r = 0; r < 4; r++) acc[i][j][r] = 0.f;

    auto LOAD = [&](int t, int st) {
        const long kt = (long)t * BK;
        const uint32_t aoff = sbase + (uint32_t)st * STAGE_BYTES;
        const uint32_t boff = aoff + A_STAGE_BYTES;
        #pragma unroll
        for (int i = 0; i < 2; i++) {
            int idx = tid + i * 256;
            int row = idx >> 2, q = idx & 3;
            CPASYNC(aoff + (uint32_t)((row * 40 + q * 8) * 2),
                    A + (long)(row0 + row) * K3P + kt + q * 8);
            CPASYNC(boff + (uint32_t)((row * 40 + q * 8) * 2),
                    B + (long)(col0 + row) * K3P + kt + q * 8);
        }
        CP_COMMIT();
    };

    const int l15 = lid & 15, lh = lid >> 4;

    #pragma unroll
    for (int s = 0; s < STAGES - 1; s++) LOAD(s, s);

    for (int t = 0; t < nT; t++) {
        CP_WAIT(STAGES - 2);
        __syncthreads();
        const uint32_t aoff = sbase + (uint32_t)(t & (STAGES - 1)) * STAGE_BYTES;
        const uint32_t boff = aoff + A_STAGE_BYTES;
        Frag f;
        load_afrags(f, aoff, wm, l15, lh);
        #pragma unroll
        for (int ks = 0; ks < 2; ks++) {
            #pragma unroll
            for (int j2 = 0; j2 < 4; j2++) {
                uint32_t r0, r1, r2, r3;
                uint32_t baddr = boff + (uint32_t)(((wn * 64 + j2 * 16 + l15) * 40 + lh * 8 + ks * 16) * 2);
                LDMX4(r0, r1, r2, r3, baddr);
                MMA(acc[0][2*j2],   f.a[ks][0], r0, r2);
                MMA(acc[1][2*j2],   f.a[ks][1], r0, r2);
                MMA(acc[0][2*j2+1], f.a[ks][0], r1, r3);
                MMA(acc[1][2*j2+1], f.a[ks][1], r1, r3);
            }
        }
        int nt = t + STAGES - 1;
        if (nt < nT) LOAD(nt, nt & (STAGES - 1));
        else         CP_COMMIT();
    }

    // epilogue
    const int g = lid >> 2, tig = lid & 3;
    #pragma unroll
    for (int i = 0; i < 2; i++) {
        #pragma unroll
        for (int j = 0; j < 8; j++) {
            const int c = col0 + wn * 64 + j * 8 + 2 * tig;
            #pragma unroll
            for (int s = 0; s < 2; s++) {
                const int r = row0 + wm * 32 + i * 16 + g + s * 8;
                const float v0 = acc[i][j][2*s], v1 = acc[i][j][2*s+1];
                if (wsel == 0) {
                    store_split_pair(reinterpret_cast<uint32_t*>(Qo + (long)r * K3P + 3L * c), v0, v1, 1);
                } else if (wsel == 1) {
                    store_split_pair(reinterpret_cast<uint32_t*>(Ko + (long)r * K3P + 3L * c), v0, v1, 2);
                } else {
                    unsigned short h0, l0, h1, l1;
                    split_us(v0, h0, l0);
                    split_us(v1, h1, l1);
                    const int bz = r >> 11, tok = r & (SEQ - 1);
                    __nv_bfloat16* Vb = Vo + (long)bz * K3S * DIM;
                    uint32_t uh = (uint32_t)h0 | ((uint32_t)h1 << 16);
                    uint32_t ul = (uint32_t)l0 | ((uint32_t)l1 << 16);
                    long rb = (long)(3 * tok) * DIM + c;
                    *reinterpret_cast<uint32_t*>(&Vb[rb])           = uh;
                    *reinterpret_cast<uint32_t*>(&Vb[rb + DIM])     = uh;
                    *reinterpret_cast<uint32_t*>(&Vb[rb + 2 * DIM]) = ul;
                }
            }
        }
    }
}

// ---------------- scores GEMM: triangular-packed grid ----------------
// grid (136, 1, BATCH); linear t -> (by, bx) with bx <= by
__global__ void __launch_bounds__(THREADS, 2)
scores_gemm(const __nv_bfloat16* __restrict__ Q, const __nv_bfloat16* __restrict__ Kk,
            float* __restrict__ Sc, float alpha)
{
    extern __shared__ char smem[];
    const uint32_t sbase = smem_u32(smem);

    int t_lin = blockIdx.x;
    int by = (int)((sqrtf(8.f * t_lin + 1.f) - 1.f) * 0.5f);
    while ((by + 1) * (by + 2) / 2 <= t_lin) by++;
    while (by * (by + 1) / 2 > t_lin) by--;
    const int bx = t_lin - by * (by + 1) / 2;

    const __nv_bfloat16* A = Q  + (long)blockIdx.z * SEQ * K3P;
    const __nv_bfloat16* B = Kk + (long)blockIdx.z * SEQ * K3P;
    float* C = Sc + (long)blockIdx.z * SEQ * SEQ;

    const int tid = threadIdx.x, lid = tid & 31, wid = tid >> 5;
    const int wm = wid & 3, wn = wid >> 2;
    const int row0 = by * BM, col0 = bx * BN;
    const int nT = K3P / BK;

    float acc[2][8][4];
    #pragma unroll
    for (int i = 0; i < 2; i++)
        #pragma unroll
        for (int j = 0; j < 8; j++)
            #pragma unroll
            for (int r = 0; r < 4; r++) acc[i][j][r] = 0.f;

    auto LOAD = [&](int t, int st) {
        const long kt = (long)t * BK;
        const uint32_t aoff = sbase + (uint32_t)st * STAGE_BYTES;
        const uint32_t boff = aoff + A_STAGE_BYTES;
        #pragma unroll
        for (int i = 0; i < 2; i++) {
            int idx = tid + i * 256;
            int row = idx >> 2, q = idx & 3;
            CPASYNC(aoff + (uint32_t)((row * 40 + q * 8) * 2),
                    A + (long)(row0 + row) * K3P + kt + q * 8);
            CPASYNC(boff + (uint32_t)((row * 40 + q * 8) * 2),
                    B + (long)(col0 + row) * K3P + kt + q * 8);
        }
        CP_COMMIT();
    };

    const int l15 = lid & 15, lh = lid >> 4;

    #pragma unroll
    for (int s = 0; s < STAGES - 1; s++) LOAD(s, s);

    for (int t = 0; t < nT; t++) {
        CP_WAIT(STAGES - 2);
        __syncthreads();
        const uint32_t aoff = sbase + (uint32_t)(t & (STAGES - 1)) * STAGE_BYTES;
        const uint32_t boff = aoff + A_STAGE_BYTES;
        Frag f;
        load_afrags(f, aoff, wm, l15, lh);
        #pragma unroll
        for (int ks = 0; ks < 2; ks++) {
            #pragma unroll
            for (int j2 = 0; j2 < 4; j2++) {
                uint32_t r0, r1, r2, r3;
                uint32_t baddr = boff + (uint32_t)(((wn * 64 + j2 * 16 + l15) * 40 + lh * 8 + ks * 16) * 2);
                LDMX4(r0, r1, r2, r3, baddr);
                MMA(acc[0][2*j2],   f.a[ks][0], r0, r2);
                MMA(acc[1][2*j2],   f.a[ks][1], r0, r2);
                MMA(acc[0][2*j2+1], f.a[ks][0], r1, r3);
                MMA(acc[1][2*j2+1], f.a[ks][1], r1, r3);
            }
        }
        int nt = t + STAGES - 1;
        if (nt < nT) LOAD(nt, nt & (STAGES - 1));
        else         CP_COMMIT();
    }

    const int g = lid >> 2, tig = lid & 3;
    #pragma unroll
    for (int i = 0; i < 2; i++) {
        #pragma unroll
        for (int j = 0; j < 8; j++) {
            const int c = col0 + wn * 64 + j * 8 + 2 * tig;
            #pragma unroll
            for (int s = 0; s < 2; s++) {
                const int r = row0 + wm * 32 + i * 16 + g + s * 8;
                float2 o = make_float2(acc[i][j][2*s] * alpha, acc[i][j][2*s+1] * alpha);
                *reinterpret_cast<float2*>(&C[(long)r * SEQ + c]) = o;
            }
        }
    }
}

// ---------------- PV GEMM: NN, causal k-limit, longest-first ----------------
__global__ void __launch_bounds__(THREADS, 2)
pv_gemm(const __nv_bfloat16* __restrict__ P, const __nv_bfloat16* __restrict__ V,
        float* __restrict__ Out)
{
    extern __shared__ char smem[];
    const uint32_t sbase = smem_u32(smem);

    const int by = gridDim.y - 1 - blockIdx.y;    // longest K first
    const __nv_bfloat16* A = P + (long)blockIdx.z * SEQ * K3S;
    const __nv_bfloat16* B = V + (long)blockIdx.z * K3S * DIM;
    float* C = Out + (long)blockIdx.z * SEQ * DIM;

    const int tid = threadIdx.x, lid = tid & 31, wid = tid >> 5;
    const int wm = wid & 3, wn = wid >> 2;
    const int row0 = by * BM, col0 = blockIdx.x * BN;
    const int nT = 3 * (by + 1) * BM / BK;

    float acc[2][8][4];
    #pragma unroll
    for (int i = 0; i < 2; i++)
        #pragma unroll
        for (int j = 0; j < 8; j++)
            #pragma unroll
            for (int r = 0; r < 4; r++) acc[i][j][r] = 0.f;

    auto LOAD = [&](int t, int st) {
        const long kt = (long)t * BK;
        const uint32_t aoff = sbase + (uint32_t)st * STAGE_BYTES;
        const uint32_t boff = aoff + A_STAGE_BYTES;
        #pragma unroll
        for (int i = 0; i < 2; i++) {
            int idx = tid + i * 256;
            int row = idx >> 2, q = idx & 3;
            CPASYNC(aoff + (uint32_t)((row * 40 + q * 8) * 2),
                    A + (long)(row0 + row) * K3S + kt + q * 8);
            int kr = idx >> 4, c = (idx & 15) * 8;
            CPASYNC(boff + (uint32_t)((kr * 136 + c) * 2),
                    B + (long)(kt + kr) * DIM + col0 + c);
        }
        CP_COMMIT();
    };

    const int l15 = lid & 15, lh = lid >> 4;

    #pragma unroll
    for (int s = 0; s < STAGES - 1; s++) LOAD(s, s);   // nT >= 12 always

    for (int t = 0; t < nT; t++) {
        CP_WAIT(STAGES - 2);
        __syncthreads();
        const uint32_t aoff = sbase + (uint32_t)(t & (STAGES - 1)) * STAGE_BYTES;
        const uint32_t boff = aoff + A_STAGE_BYTES;
        Frag f;
        load_afrags(f, aoff, wm, l15, lh);
        #pragma unroll
        for (int ks = 0; ks < 2; ks++) {
            #pragma unroll
            for (int j2 = 0; j2 < 4; j2++) {
                uint32_t r0, r1, r2, r3;
                uint32_t baddr = boff + (uint32_t)(((ks * 16 + l15) * 136 + wn * 64 + j2 * 16 + lh * 8) * 2);
                LDMX4T(r0, r1, r2, r3, baddr);
                MMA(acc[0][2*j2],   f.a[ks][0], r0, r1);
                MMA(acc[1][2*j2],   f.a[ks][1], r0, r1);
                MMA(acc[0][2*j2+1], f.a[ks][0], r2, r3);
                MMA(acc[1][2*j2+1], f.a[ks][1], r2, r3);
            }
        }
        int nt = t + STAGES - 1;
        if (nt < nT) LOAD(nt, nt & (STAGES - 1));
        else         CP_COMMIT();
    }

    const int g = lid >> 2, tig = lid & 3;
    #pragma unroll
    for (int i = 0; i < 2; i++) {
        #pragma unroll
        for (int j = 0; j < 8; j++) {
            const int c = col0 + wn * 64 + j * 8 + 2 * tig;
            #pragma unroll
            for (int s = 0; s < 2; s++) {
                const int r = row0 + wm * 32 + i * 16 + g + s * 8;
                float2 o = make_float2(acc[i][j][2*s], acc[i][j][2*s+1]);
                *reinterpret_cast<float2*>(&C[(long)r * DIM + c]) = o;
            }
        }
    }
}

// ---------------- softmax: fp32 scores -> split-bf16 P (A-layout) ----------------
__global__ __launch_bounds__(256)
void softmax_p2(const float* __restrict__ Sc, const int* __restrict__ mask,
                __nv_bfloat16* __restrict__ P2)
{
    __shared__ float e[SEQ];
    __shared__ float red[256];
    const int q = SEQ - 1 - blockIdx.x;   // longest rows first
    const int b = blockIdx.y, tid = threadIdx.x;
    const float* row = Sc + ((long)b * SEQ + q) * SEQ;
    const int* mk = mask + (long)b * SEQ;
    __nv_bfloat16* pr = P2 + ((long)b * SEQ + q) * (long)K3S;

    float mx = -CUDART_INF_F;
    for (int c = tid; c <= q; c += 256)
        if (mk[c]) mx = fmaxf(mx, row[c]);
    red[tid] = mx; __syncthreads();
    #pragma unroll
    for (int s = 128; s > 0; s >>= 1) {
        if (tid < s) red[tid] = fmaxf(red[tid], red[tid + s]);
        __syncthreads();
    }
    mx = red[0]; __syncthreads();

    float sum = 0.f;
    for (int c = tid; c <= q; c += 256) {
        float v = mk[c] ? __expf(row[c] - mx) : 0.f;
        e[c] = v; sum += v;
    }
    red[tid] = sum; __syncthreads();
    #pragma unroll
    for (int s = 128; s > 0; s >>= 1) {
        if (tid < s) red[tid] += red[tid + s];
        __syncthreads();
    }
    const float inv = 1.f / red[0];
    __syncthreads();

    for (int c = tid; c < SEQ; c += 256) {
        float v = (c <= q) ? e[c] * inv : 0.f;
        unsigned short h, l;
        split_us(v, h, l);
        pr[3*c]   = __ushort_as_bfloat16(h);
        pr[3*c+1] = __ushort_as_bfloat16(l);
        pr[3*c+2] = __ushort_as_bfloat16(h);
    }
}

// ---------------- host ----------------
extern "C" void kernel_launch(void* const* d_in, const int* in_sizes, int n_in,
                              void* d_out, int out_size)
{
    const float* x    = (const float*)d_in[0];
    const int*   mask = (const int*)  d_in[1];
    const float* Wq   = (const float*)d_in[2];
    const float* Wk   = (const float*)d_in[3];
    const float* Wv   = (const float*)d_in[4];
    float* out = (float*)d_out;

    __nv_bfloat16 *x2p, *wq2, *wk2, *wv2, *q2p, *k2p, *v2p, *p2p;
    float* sp;
    cudaGetSymbolAddress((void**)&x2p, g_x2);
    cudaGetSymbolAddress((void**)&wq2, g_Wq2);
    cudaGetSymbolAddress((void**)&wk2, g_Wk2);
    cudaGetSymbolAddress((void**)&wv2, g_Wv2);
    cudaGetSymbolAddress((void**)&q2p, g_Q2);
    cudaGetSymbolAddress((void**)&k2p, g_K2);
    cudaGetSymbolAddress((void**)&v2p, g_V2);
    cudaGetSymbolAddress((void**)&sp,  g_S);
    cudaGetSymbolAddress((void**)&p2p, g_P2);

    static bool attr_done = false;
    if (!attr_done) {
        cudaFuncSetAttribute(qkv_gemm,    cudaFuncAttributeMaxDynamicSharedMemorySize, SMEM_TOTAL);
        cudaFuncSetAttribute(scores_gemm, cudaFuncAttributeMaxDynamicSharedMemorySize, SMEM_TOTAL);
        cudaFuncSetAttribute(pv_gemm,     cudaFuncAttributeMaxDynamicSharedMemorySize, SMEM_TOTAL);
        attr_done = true;
    }

    const long nx4 = (long)BATCH * SEQ * DIM / 4;
    const long nw4 = (long)DIM * DIM / 4;
    convert_x<<<(unsigned)((nx4 + 255) / 256), 256>>>((const float4*)x, (uint2*)x2p, nx4);
    convert_w<<<dim3((unsigned)((nw4 + 255) / 256), 3), 256>>>(
        (const float4*)Wq, (const float4*)Wk, (const float4*)Wv,
        (uint2*)wq2, (uint2*)wk2, (uint2*)wv2, nw4);

    // merged QKV projections
    dim3 gP(24, (BATCH * SEQ) / BM, 1);                  // (24, 64)
    qkv_gemm<<<gP, THREADS, SMEM_TOTAL>>>(x2p, wq2, wk2, wv2, q2p, k2p, v2p);

    // scores: triangular-packed grid
    dim3 gS(136, 1, BATCH);
    scores_gemm<<<gS, THREADS, SMEM_TOTAL>>>(q2p, k2p, sp, 1.f / 32.f);

    // softmax -> split P
    softmax_p2<<<dim3(SEQ, BATCH), 256>>>(sp, mask, p2p);

    // O = P @ V
    dim3 gO(DIM / BN, SEQ / BM, BATCH);                  // (8, 16, 4)
    pv_gemm<<<gO, THREADS, SMEM_TOTAL>>>(p2p, v2p, out);
}

// round 7
// speedup vs baseline: 2.8107x; 1.0056x over previous
#include <cuda_runtime.h>
#include <cuda_bf16.h>
#include <math_constants.h>
#include <cstdint>

#define BATCH 4
#define SEQ   2048
#define DIM   1024
#define K3P   (3 * DIM)   // 3072
#define K3S   (3 * SEQ)   // 6144

#define BM 128
#define BN 128
#define BK 64
#define THREADS 256
#define STAGES 3
#define A_STAGE_BYTES 18432u           // 128 rows x 72 elems x 2B (144B stride)
#define STAGE_BYTES   36864u           // A + B region per stage
#define SMEM_TOTAL (STAGES * STAGE_BYTES)   // 110592 -> 2 CTA/SM (216KB of 228KB)

// ---------------- scratch ----------------
__device__ __nv_bfloat16 g_x2 [(long)BATCH * SEQ * K3P];   // x  split A-layout (hi,lo,hi)
__device__ __nv_bfloat16 g_Wq2[(long)DIM * K3P];           // W  split B-layout (hi,hi,lo)
__device__ __nv_bfloat16 g_Wk2[(long)DIM * K3P];
__device__ __nv_bfloat16 g_Wv2[(long)DIM * K3P];
__device__ __nv_bfloat16 g_Q2 [(long)BATCH * SEQ * K3P];   // Q  split A-layout
__device__ __nv_bfloat16 g_K2 [(long)BATCH * SEQ * K3P];   // K  split B-layout
__device__ __nv_bfloat16 g_V2 [(long)BATCH * K3S * DIM];   // V  split rows (hi,hi,lo) x [k][n]
__device__ float         g_S  [(long)BATCH * SEQ * SEQ];
__device__ __nv_bfloat16 g_P2 [(long)BATCH * SEQ * K3S];   // P  split A-layout

// ---------------- asm helpers ----------------
__device__ __forceinline__ uint32_t smem_u32(const void* p) {
    uint32_t a;
    asm("{ .reg .u64 t; cvta.to.shared.u64 t, %1; cvt.u32.u64 %0, t; }" : "=r"(a) : "l"(p));
    return a;
}
#define LDMX4(r0,r1,r2,r3,addr) \
    asm volatile("ldmatrix.sync.aligned.m8n8.x4.shared.b16 {%0,%1,%2,%3}, [%4];" \
                 : "=r"(r0),"=r"(r1),"=r"(r2),"=r"(r3) : "r"(addr))
#define LDMX4T(r0,r1,r2,r3,addr) \
    asm volatile("ldmatrix.sync.aligned.m8n8.x4.trans.shared.b16 {%0,%1,%2,%3}, [%4];" \
                 : "=r"(r0),"=r"(r1),"=r"(r2),"=r"(r3) : "r"(addr))
#define MMA(c,a,b0,b1) \
    asm volatile("mma.sync.aligned.m16n8k16.row.col.f32.bf16.bf16.f32 " \
                 "{%0,%1,%2,%3}, {%4,%5,%6,%7}, {%8,%9}, {%0,%1,%2,%3};" \
                 : "+f"((c)[0]),"+f"((c)[1]),"+f"((c)[2]),"+f"((c)[3]) \
                 : "r"((a)[0]),"r"((a)[1]),"r"((a)[2]),"r"((a)[3]),"r"(b0),"r"(b1))
#define CPASYNC(s,g) \
    asm volatile("cp.async.cg.shared.global [%0], [%1], 16;" :: "r"(s),"l"(g))
#define CP_COMMIT() asm volatile("cp.async.commit_group;" ::: "memory")
#define CP_WAIT(N)  asm volatile("cp.async.wait_group %0;" :: "n"(N) : "memory")

__device__ __forceinline__ void split_us(float v, unsigned short& h, unsigned short& l) {
    __nv_bfloat16 hb = __float2bfloat16(v);
    __nv_bfloat16 lb = __float2bfloat16(v - __bfloat162float(hb));
    h = __bfloat16_as_ushort(hb);
    l = __bfloat16_as_ushort(lb);
}

__device__ __forceinline__ void store_split_pair(uint32_t* p, float v0, float v1, int lay) {
    unsigned short h0, l0, h1, l1;
    split_us(v0, h0, l0);
    split_us(v1, h1, l1);
    if (lay == 1) {        // A-layout hi,lo,hi
        p[0] = (uint32_t)h0 | ((uint32_t)l0 << 16);
        p[1] = (uint32_t)h0 | ((uint32_t)h1 << 16);
        p[2] = (uint32_t)l1 | ((uint32_t)h1 << 16);
    } else {               // B-layout hi,hi,lo
        p[0] = (uint32_t)h0 | ((uint32_t)h0 << 16);
        p[1] = (uint32_t)l0 | ((uint32_t)h1 << 16);
        p[2] = (uint32_t)h1 | ((uint32_t)l1 << 16);
    }
}

// ---------------- input conversions ----------------
__global__ void convert_x(const float4* __restrict__ in, uint2* __restrict__ out, long n4) {
    long i = (long)blockIdx.x * blockDim.x + threadIdx.x;
    if (i >= n4) return;
    float4 v = in[i];
    unsigned short h[4], l[4];
    split_us(v.x, h[0], l[0]); split_us(v.y, h[1], l[1]);
    split_us(v.z, h[2], l[2]); split_us(v.w, h[3], l[3]);
    unsigned short t[12];
    #pragma unroll
    for (int e = 0; e < 4; e++) { t[3*e] = h[e]; t[3*e+1] = l[e]; t[3*e+2] = h[e]; }
    uint2* o = out + 3 * i;
    #pragma unroll
    for (int j = 0; j < 3; j++) {
        uint2 u;
        u.x = (uint32_t)t[4*j]   | ((uint32_t)t[4*j+1] << 16);
        u.y = (uint32_t)t[4*j+2] | ((uint32_t)t[4*j+3] << 16);
        o[j] = u;
    }
}

__global__ void convert_w(const float4* __restrict__ wq, const float4* __restrict__ wk,
                          const float4* __restrict__ wv,
                          uint2* __restrict__ oq, uint2* __restrict__ ok,
                          uint2* __restrict__ ov, long n4) {
    long i = (long)blockIdx.x * blockDim.x + threadIdx.x;
    if (i >= n4) return;
    const float4* in = (blockIdx.y == 0) ? wq : (blockIdx.y == 1) ? wk : wv;
    uint2* out = (blockIdx.y == 0) ? oq : (blockIdx.y == 1) ? ok : ov;
    float4 v = in[i];
    unsigned short h[4], l[4];
    split_us(v.x, h[0], l[0]); split_us(v.y, h[1], l[1]);
    split_us(v.z, h[2], l[2]); split_us(v.w, h[3], l[3]);
    unsigned short t[12];
    #pragma unroll
    for (int e = 0; e < 4; e++) { t[3*e] = h[e]; t[3*e+1] = h[e]; t[3*e+2] = l[e]; }
    uint2* o = out + 3 * i;
    #pragma unroll
    for (int j = 0; j < 3; j++) {
        uint2 u;
        u.x = (uint32_t)t[4*j]   | ((uint32_t)t[4*j+1] << 16);
        u.y = (uint32_t)t[4*j+2] | ((uint32_t)t[4*j+3] << 16);
        o[j] = u;
    }
}

// ================= GEMM engine pieces (BK=64, 3-stage) =================
// NT compute step for one stage
#define COMPUTE_NT(aoff, boff)                                                          \
    {                                                                                   \
        _Pragma("unroll")                                                               \
        for (int ks = 0; ks < 4; ks++) {                                                \
            uint32_t a0[4], a1[4];                                                      \
            uint32_t abase = (aoff) + (uint32_t)(((wm * 32 + l15) * 72 + lh * 8 + ks * 16) * 2); \
            LDMX4(a0[0], a0[1], a0[2], a0[3], abase);                                   \
            LDMX4(a1[0], a1[1], a1[2], a1[3], abase + 16 * 144);                        \
            _Pragma("unroll")                                                           \
            for (int j2 = 0; j2 < 4; j2++) {                                            \
                uint32_t r0, r1, r2, r3;                                                \
                uint32_t baddr = (boff) + (uint32_t)(((wn * 64 + j2 * 16 + l15) * 72 + lh * 8 + ks * 16) * 2); \
                LDMX4(r0, r1, r2, r3, baddr);                                           \
                MMA(acc[0][2*j2],   a0, r0, r2);                                        \
                MMA(acc[1][2*j2],   a1, r0, r2);                                        \
                MMA(acc[0][2*j2+1], a0, r1, r3);                                        \
                MMA(acc[1][2*j2+1], a1, r1, r3);                                        \
            }                                                                           \
        }                                                                               \
    }

#define COMPUTE_NN(aoff, boff)                                                          \
    {                                                                                   \
        _Pragma("unroll")                                                               \
        for (int ks = 0; ks < 4; ks++) {                                                \
            uint32_t a0[4], a1[4];                                                      \
            uint32_t abase = (aoff) + (uint32_t)(((wm * 32 + l15) * 72 + lh * 8 + ks * 16) * 2); \
            LDMX4(a0[0], a0[1], a0[2], a0[3], abase);                                   \
            LDMX4(a1[0], a1[1], a1[2], a1[3], abase + 16 * 144);                        \
            _Pragma("unroll")                                                           \
            for (int j2 = 0; j2 < 4; j2++) {                                            \
                uint32_t r0, r1, r2, r3;                                                \
                uint32_t baddr = (boff) + (uint32_t)(((ks * 16 + l15) * 136 + wn * 64 + j2 * 16 + lh * 8) * 2); \
                LDMX4T(r0, r1, r2, r3, baddr);                                          \
                MMA(acc[0][2*j2],   a0, r0, r1);                                        \
                MMA(acc[1][2*j2],   a1, r0, r1);                                        \
                MMA(acc[0][2*j2+1], a0, r2, r3);                                        \
                MMA(acc[1][2*j2+1], a1, r2, r3);                                        \
            }                                                                           \
        }                                                                               \
    }

// main loop skeleton: LOADFN(t, stage) must be a lambda
#define MAINLOOP(NTtiles, LOADFN, COMPUTE_MACRO)                                        \
    LOADFN(0, 0);                                                                       \
    LOADFN(1, 1);                                                                       \
    {                                                                                   \
        int cs = 0;                                                                     \
        for (int t = 0; t < (NTtiles); t++) {                                           \
            if (t + 2 < (NTtiles)) { CP_WAIT(1); } else { CP_WAIT(0); }                 \
            __syncthreads();                                                            \
            int ldst = cs + 2; if (ldst >= 3) ldst -= 3;                                \
            if (t + 2 < (NTtiles)) LOADFN(t + 2, ldst);                                 \
            const uint32_t aoff_ = sbase + (uint32_t)cs * STAGE_BYTES;                  \
            const uint32_t boff_ = aoff_ + A_STAGE_BYTES;                               \
            COMPUTE_MACRO(aoff_, boff_);                                                \
            cs = (cs == 2) ? 0 : cs + 1;                                                \
        }                                                                               \
    }

// ---------------- merged QKV projection ----------------
__global__ void __launch_bounds__(THREADS, 2)
qkv_gemm(const __nv_bfloat16* __restrict__ A,
         const __nv_bfloat16* __restrict__ Wq, const __nv_bfloat16* __restrict__ Wk,
         const __nv_bfloat16* __restrict__ Wv,
         __nv_bfloat16* __restrict__ Qo, __nv_bfloat16* __restrict__ Ko,
         __nv_bfloat16* __restrict__ Vo)
{
    extern __shared__ char smem[];
    const uint32_t sbase = smem_u32(smem);

    const int wsel = blockIdx.x >> 3;
    const __nv_bfloat16* B = (wsel == 0) ? Wq : (wsel == 1) ? Wk : Wv;

    const int tid = threadIdx.x, lid = tid & 31, wid = tid >> 5;
    const int wm = wid & 3, wn = wid >> 2;
    const int row0 = blockIdx.y * BM, col0 = (blockIdx.x & 7) * BN;
    const int nT = K3P / BK;   // 48

    float acc[2][8][4];
    #pragma unroll
    for (int i = 0; i < 2; i++)
        #pragma unroll
        for (int j = 0; j < 8; j++)
            #pragma unroll
            for (int r = 0; r < 4; r++) acc[i][j][r] = 0.f;

    auto LOAD = [&](int t, int st) {
        const long kt = (long)t * BK;
        const uint32_t aoff = sbase + (uint32_t)st * STAGE_BYTES;
        const uint32_t boff = aoff + A_STAGE_BYTES;
        #pragma unroll
        for (int i = 0; i < 4; i++) {
            int idx = tid + i * 256;
            int row = idx >> 3, q = idx & 7;
            CPASYNC(aoff + (uint32_t)(row * 144 + q * 16),
                    A + (long)(row0 + row) * K3P + kt + q * 8);
            CPASYNC(boff + (uint32_t)(row * 144 + q * 16),
                    B + (long)(col0 + row) * K3P + kt + q * 8);
        }
        CP_COMMIT();
    };

    const int l15 = lid & 15, lh = lid >> 4;

    MAINLOOP(nT, LOAD, COMPUTE_NT);

    const int g = lid >> 2, tig = lid & 3;
    #pragma unroll
    for (int i = 0; i < 2; i++) {
        #pragma unroll
        for (int j = 0; j < 8; j++) {
            const int c = col0 + wn * 64 + j * 8 + 2 * tig;
            #pragma unroll
            for (int s = 0; s < 2; s++) {
                const int r = row0 + wm * 32 + i * 16 + g + s * 8;
                const float v0 = acc[i][j][2*s], v1 = acc[i][j][2*s+1];
                if (wsel == 0) {
                    store_split_pair(reinterpret_cast<uint32_t*>(Qo + (long)r * K3P + 3L * c), v0, v1, 1);
                } else if (wsel == 1) {
                    store_split_pair(reinterpret_cast<uint32_t*>(Ko + (long)r * K3P + 3L * c), v0, v1, 2);
                } else {
                    unsigned short h0, l0, h1, l1;
                    split_us(v0, h0, l0);
                    split_us(v1, h1, l1);
                    const int bz = r >> 11, tok = r & (SEQ - 1);
                    __nv_bfloat16* Vb = Vo + (long)bz * K3S * DIM;
                    uint32_t uh = (uint32_t)h0 | ((uint32_t)h1 << 16);
                    uint32_t ul = (uint32_t)l0 | ((uint32_t)l1 << 16);
                    long rb = (long)(3 * tok) * DIM + c;
                    *reinterpret_cast<uint32_t*>(&Vb[rb])           = uh;
                    *reinterpret_cast<uint32_t*>(&Vb[rb + DIM])     = uh;
                    *reinterpret_cast<uint32_t*>(&Vb[rb + 2 * DIM]) = ul;
                }
            }
        }
    }
}

// ---------------- scores GEMM: triangular-packed grid ----------------
__global__ void __launch_bounds__(THREADS, 2)
scores_gemm(const __nv_bfloat16* __restrict__ Q, const __nv_bfloat16* __restrict__ Kk,
            float* __restrict__ Sc, float alpha)
{
    extern __shared__ char smem[];
    const uint32_t sbase = smem_u32(smem);

    int t_lin = blockIdx.x;
    int by = (int)((sqrtf(8.f * t_lin + 1.f) - 1.f) * 0.5f);
    while ((by + 1) * (by + 2) / 2 <= t_lin) by++;
    while (by * (by + 1) / 2 > t_lin) by--;
    const int bx = t_lin - by * (by + 1) / 2;

    const __nv_bfloat16* A = Q  + (long)blockIdx.z * SEQ * K3P;
    const __nv_bfloat16* B = Kk + (long)blockIdx.z * SEQ * K3P;
    float* C = Sc + (long)blockIdx.z * SEQ * SEQ;

    const int tid = threadIdx.x, lid = tid & 31, wid = tid >> 5;
    const int wm = wid & 3, wn = wid >> 2;
    const int row0 = by * BM, col0 = bx * BN;
    const int nT = K3P / BK;

    float acc[2][8][4];
    #pragma unroll
    for (int i = 0; i < 2; i++)
        #pragma unroll
        for (int j = 0; j < 8; j++)
            #pragma unroll
            for (int r = 0; r < 4; r++) acc[i][j][r] = 0.f;

    auto LOAD = [&](int t, int st) {
        const long kt = (long)t * BK;
        const uint32_t aoff = sbase + (uint32_t)st * STAGE_BYTES;
        const uint32_t boff = aoff + A_STAGE_BYTES;
        #pragma unroll
        for (int i = 0; i < 4; i++) {
            int idx = tid + i * 256;
            int row = idx >> 3, q = idx & 7;
            CPASYNC(aoff + (uint32_t)(row * 144 + q * 16),
                    A + (long)(row0 + row) * K3P + kt + q * 8);
            CPASYNC(boff + (uint32_t)(row * 144 + q * 16),
                    B + (long)(col0 + row) * K3P + kt + q * 8);
        }
        CP_COMMIT();
    };

    const int l15 = lid & 15, lh = lid >> 4;

    MAINLOOP(nT, LOAD, COMPUTE_NT);

    const int g = lid >> 2, tig = lid & 3;
    #pragma unroll
    for (int i = 0; i < 2; i++) {
        #pragma unroll
        for (int j = 0; j < 8; j++) {
            const int c = col0 + wn * 64 + j * 8 + 2 * tig;
            #pragma unroll
            for (int s = 0; s < 2; s++) {
                const int r = row0 + wm * 32 + i * 16 + g + s * 8;
                float2 o = make_float2(acc[i][j][2*s] * alpha, acc[i][j][2*s+1] * alpha);
                *reinterpret_cast<float2*>(&C[(long)r * SEQ + c]) = o;
            }
        }
    }
}

// ---------------- PV GEMM: NN, causal k-limit, longest-first ----------------
__global__ void __launch_bounds__(THREADS, 2)
pv_gemm(const __nv_bfloat16* __restrict__ P, const __nv_bfloat16* __restrict__ V,
        float* __restrict__ Out)
{
    extern __shared__ char smem[];
    const uint32_t sbase = smem_u32(smem);

    const int by = gridDim.y - 1 - blockIdx.y;    // longest K first
    const __nv_bfloat16* A = P + (long)blockIdx.z * SEQ * K3S;
    const __nv_bfloat16* B = V + (long)blockIdx.z * K3S * DIM;
    float* C = Out + (long)blockIdx.z * SEQ * DIM;

    const int tid = threadIdx.x, lid = tid & 31, wid = tid >> 5;
    const int wm = wid & 3, wn = wid >> 2;
    const int row0 = by * BM, col0 = blockIdx.x * BN;
    const int nT = 3 * (by + 1) * BM / BK;        // 6*(by+1), >= 6

    float acc[2][8][4];
    #pragma unroll
    for (int i = 0; i < 2; i++)
        #pragma unroll
        for (int j = 0; j < 8; j++)
            #pragma unroll
            for (int r = 0; r < 4; r++) acc[i][j][r] = 0.f;

    auto LOAD = [&](int t, int st) {
        const long kt = (long)t * BK;
        const uint32_t aoff = sbase + (uint32_t)st * STAGE_BYTES;
        const uint32_t boff = aoff + A_STAGE_BYTES;
        #pragma unroll
        for (int i = 0; i < 4; i++) {
            int idx = tid + i * 256;
            int row = idx >> 3, q = idx & 7;
            CPASYNC(aoff + (uint32_t)(row * 144 + q * 16),
                    A + (long)(row0 + row) * K3S + kt + q * 8);
            int kr = idx >> 4, c = (idx & 15) * 8;
            CPASYNC(boff + (uint32_t)(kr * 272 + c * 2),
                    B + (long)(kt + kr) * DIM + col0 + c);
        }
        CP_COMMIT();
    };

    const int l15 = lid & 15, lh = lid >> 4;

    MAINLOOP(nT, LOAD, COMPUTE_NN);

    const int g = lid >> 2, tig = lid & 3;
    #pragma unroll
    for (int i = 0; i < 2; i++) {
        #pragma unroll
        for (int j = 0; j < 8; j++) {
            const int c = col0 + wn * 64 + j * 8 + 2 * tig;
            #pragma unroll
            for (int s = 0; s < 2; s++) {
                const int r = row0 + wm * 32 + i * 16 + g + s * 8;
                float2 o = make_float2(acc[i][j][2*s], acc[i][j][2*s+1]);
                *reinterpret_cast<float2*>(&C[(long)r * DIM + c]) = o;
            }
        }
    }
}

// ---------------- softmax: fp32 scores -> split-bf16 P (A-layout) ----------------
__global__ __launch_bounds__(256)
void softmax_p2(const float* __restrict__ Sc, const int* __restrict__ mask,
                __nv_bfloat16* __restrict__ P2)
{
    __shared__ float e[SEQ];
    __shared__ float red[256];
    const int q = SEQ - 1 - blockIdx.x;   // longest rows first
    const int b = blockIdx.y, tid = threadIdx.x;
    const float* row = Sc + ((long)b * SEQ + q) * SEQ;
    const int* mk = mask + (long)b * SEQ;
    __nv_bfloat16* pr = P2 + ((long)b * SEQ + q) * (long)K3S;

    float mx = -CUDART_INF_F;
    for (int c = tid; c <= q; c += 256)
        if (mk[c]) mx = fmaxf(mx, row[c]);
    red[tid] = mx; __syncthreads();
    #pragma unroll
    for (int s = 128; s > 0; s >>= 1) {
        if (tid < s) red[tid] = fmaxf(red[tid], red[tid + s]);
        __syncthreads();
    }
    mx = red[0]; __syncthreads();

    float sum = 0.f;
    for (int c = tid; c <= q; c += 256) {
        float v = mk[c] ? __expf(row[c] - mx) : 0.f;
        e[c] = v; sum += v;
    }
    red[tid] = sum; __syncthreads();
    #pragma unroll
    for (int s = 128; s > 0; s >>= 1) {
        if (tid < s) red[tid] += red[tid + s];
        __syncthreads();
    }
    const float inv = 1.f / red[0];
    __syncthreads();

    for (int c = tid; c < SEQ; c += 256) {
        float v = (c <= q) ? e[c] * inv : 0.f;
        unsigned short h, l;
        split_us(v, h, l);
        pr[3*c]   = __ushort_as_bfloat16(h);
        pr[3*c+1] = __ushort_as_bfloat16(l);
        pr[3*c+2] = __ushort_as_bfloat16(h);
    }
}

// ---------------- host ----------------
extern "C" void kernel_launch(void* const* d_in, const int* in_sizes, int n_in,
                              void* d_out, int out_size)
{
    const float* x    = (const float*)d_in[0];
    const int*   mask = (const int*)  d_in[1];
    const float* Wq   = (const float*)d_in[2];
    const float* Wk   = (const float*)d_in[3];
    const float* Wv   = (const float*)d_in[4];
    float* out = (float*)d_out;

    __nv_bfloat16 *x2p, *wq2, *wk2, *wv2, *q2p, *k2p, *v2p, *p2p;
    float* sp;
    cudaGetSymbolAddress((void**)&x2p, g_x2);
    cudaGetSymbolAddress((void**)&wq2, g_Wq2);
    cudaGetSymbolAddress((void**)&wk2, g_Wk2);
    cudaGetSymbolAddress((void**)&wv2, g_Wv2);
    cudaGetSymbolAddress((void**)&q2p, g_Q2);
    cudaGetSymbolAddress((void**)&k2p, g_K2);
    cudaGetSymbolAddress((void**)&v2p, g_V2);
    cudaGetSymbolAddress((void**)&sp,  g_S);
    cudaGetSymbolAddress((void**)&p2p, g_P2);

    static bool attr_done = false;
    if (!attr_done) {
        cudaFuncSetAttribute(qkv_gemm,    cudaFuncAttributeMaxDynamicSharedMemorySize, SMEM_TOTAL);
        cudaFuncSetAttribute(scores_gemm, cudaFuncAttributeMaxDynamicSharedMemorySize, SMEM_TOTAL);
        cudaFuncSetAttribute(pv_gemm,     cudaFuncAttributeMaxDynamicSharedMemorySize, SMEM_TOTAL);
        attr_done = true;
    }

    const long nx4 = (long)BATCH * SEQ * DIM / 4;
    const long nw4 = (long)DIM * DIM / 4;
    convert_x<<<(unsigned)((nx4 + 255) / 256), 256>>>((const float4*)x, (uint2*)x2p, nx4);
    convert_w<<<dim3((unsigned)((nw4 + 255) / 256), 3), 256>>>(
        (const float4*)Wq, (const float4*)Wk, (const float4*)Wv,
        (uint2*)wq2, (uint2*)wk2, (uint2*)wv2, nw4);

    // merged QKV projections
    dim3 gP(24, (BATCH * SEQ) / BM, 1);                  // (24, 64)
    qkv_gemm<<<gP, THREADS, SMEM_TOTAL>>>(x2p, wq2, wk2, wv2, q2p, k2p, v2p);

    // scores: triangular-packed grid
    dim3 gS(136, 1, BATCH);
    scores_gemm<<<gS, THREADS, SMEM_TOTAL>>>(q2p, k2p, sp, 1.f / 32.f);

    // softmax -> split P
    softmax_p2<<<dim3(SEQ, BATCH), 256>>>(sp, mask, p2p);

    // O = P @ V
    dim3 gO(DIM / BN, SEQ / BM, BATCH);                  // (8, 16, 4)
    pv_gemm<<<gO, THREADS, SMEM_TOTAL>>>(p2p, v2p, out);
}